// round 1
// baseline (speedup 1.0000x reference)
#include <cuda_runtime.h>
#include <math.h>

#define BB 2
#define SS 2048
#define DD 1024
#define NH 16
#define NKV 4
#define HD 64
#define GATE_CH 12
#define EPSV 1e-6f

// Scratch (allocation-free rule: __device__ globals)
__device__ float g_q[BB * SS * NH * HD];    // [b,s,h,d]
__device__ float g_k[BB * SS * NKV * HD];   // [b,s,kvh,d]
__device__ float g_v[BB * SS * NKV * HD];
__device__ float g_y[BB * SS * DD];         // attention output, [b,s,h*hd]

// ---------------------------------------------------------------------------
// SGEMM: C[M,N] = A[M,K] @ W[K,N], row-major, fp32.
// BM=128, BN=64, BK=16, 256 threads, 8x4 per-thread microtile.
// Requires M%128==0, N%64==0, K%16==0 (true for all our shapes).
// ---------------------------------------------------------------------------
__global__ __launch_bounds__(256) void sgemm128x64(
    const float* __restrict__ A, const float* __restrict__ W,
    float* __restrict__ C, int M, int N, int K)
{
    __shared__ float As[16][128];
    __shared__ float Bs[16][64];

    const int tid = threadIdx.x;
    const int ty = tid >> 4;      // 0..15 (row group)
    const int tx = tid & 15;      // 0..15 (col group)
    const int rowBase = blockIdx.y * 128;
    const int colBase = blockIdx.x * 64;

    float acc[8][4] = {};

    for (int k0 = 0; k0 < K; k0 += 16) {
        // Load A tile: 128 rows x 16 cols = 512 float4, 2 per thread
#pragma unroll
        for (int i = 0; i < 2; i++) {
            int lin = tid + i * 256;       // 0..511
            int r = lin >> 2;
            int c4 = (lin & 3) * 4;
            float4 a = *(const float4*)(A + (size_t)(rowBase + r) * K + k0 + c4);
            As[c4 + 0][r] = a.x;
            As[c4 + 1][r] = a.y;
            As[c4 + 2][r] = a.z;
            As[c4 + 3][r] = a.w;
        }
        // Load W tile: 16 rows x 64 cols = 256 float4, 1 per thread
        {
            int r = tid >> 4;
            int c4 = (tid & 15) * 4;
            *(float4*)&Bs[r][c4] = *(const float4*)(W + (size_t)(k0 + r) * N + colBase + c4);
        }
        __syncthreads();

#pragma unroll
        for (int kk = 0; kk < 16; kk++) {
            float a[8], b[4];
#pragma unroll
            for (int i = 0; i < 8; i++) a[i] = As[kk][ty * 8 + i];
#pragma unroll
            for (int j = 0; j < 4; j++) b[j] = Bs[kk][tx * 4 + j];
#pragma unroll
            for (int i = 0; i < 8; i++)
#pragma unroll
                for (int j = 0; j < 4; j++) acc[i][j] += a[i] * b[j];
        }
        __syncthreads();
    }

#pragma unroll
    for (int i = 0; i < 8; i++) {
        float4 o = make_float4(acc[i][0], acc[i][1], acc[i][2], acc[i][3]);
        *(float4*)(C + (size_t)(rowBase + ty * 8 + i) * N + colBase + tx * 4) = o;
    }
}

// ---------------------------------------------------------------------------
// V gate epilogue: v[b,s,kvh,:] += 3*sigmoid(x[b,s,:12] @ Wg[:,kvh]) * ve[...]
// grid = B*S, block = 256 (kvh = t/64, d = t%64)
// ---------------------------------------------------------------------------
__global__ void vgate_kernel(const float* __restrict__ x,
                             const float* __restrict__ ve,
                             const float* __restrict__ Wg)
{
    int bs = blockIdx.x;
    int t = threadIdx.x;
    int kvh = t >> 6;
    const float* xr = x + (size_t)bs * DD;
    float g = 0.f;
#pragma unroll
    for (int c = 0; c < GATE_CH; c++) g += xr[c] * Wg[c * NKV + kvh];
    g = 3.f / (1.f + __expf(-g));
    size_t idx = (size_t)bs * (NKV * HD) + t;   // (bs*NKV + kvh)*HD + d
    g_v[idx] += g * ve[idx];
}

// ---------------------------------------------------------------------------
// RoPE + RMSNorm (*1.2) for q and k in place.
// grid = B*S*(NH+NKV), block = 64 (one thread per dim)
// ---------------------------------------------------------------------------
__global__ void rope_norm_kernel(const float* __restrict__ cosp,
                                 const float* __restrict__ sinp)
{
    int blk = blockIdx.x;
    int hh = blk % (NH + NKV);
    int bs = blk / (NH + NKV);
    int s = bs % SS;

    float* ptr;
    if (hh < NH) ptr = g_q + ((size_t)bs * NH + hh) * HD;
    else         ptr = g_k + ((size_t)bs * NKV + (hh - NH)) * HD;

    int d = threadIdx.x;
    int half = d & 31;
    float c  = cosp[s * 32 + half];
    float sn = sinp[s * 32 + half];
    float x1 = ptr[half];
    float x2 = ptr[half + 32];
    float rot = (d < 32) ? (x1 * c + x2 * sn) : (-x1 * sn + x2 * c);

    // block reduce sum of rot^2 over 64 lanes (2 warps)
    __shared__ float red[2];
    float v = rot * rot;
#pragma unroll
    for (int o = 16; o > 0; o >>= 1) v += __shfl_xor_sync(0xffffffffu, v, o);
    if ((d & 31) == 0) red[d >> 5] = v;
    __syncthreads();
    float total = red[0] + red[1];
    float r = rsqrtf(total * (1.f / HD) + EPSV) * 1.2f;
    ptr[d] = rot * r;
}

// ---------------------------------------------------------------------------
// Sliding-window causal attention.
// grid = B*NH*(S/128), block = 128 (one query per thread).
// K/V staged in smem in 64-key tiles; per-thread online softmax.
// ---------------------------------------------------------------------------
__global__ __launch_bounds__(128) void attn_kernel(const int* __restrict__ winp)
{
    const int win = *winp;
    int blk = blockIdx.x;
    int qt = blk % (SS / 128);
    int bh = blk / (SS / 128);
    int h = bh % NH;
    int b = bh / NH;
    int q0 = qt * 128;
    int qpos = q0 + threadIdx.x;
    int kv = h / (NH / NKV);

    const float* qptr = g_q + (((size_t)(b * SS + qpos)) * NH + h) * HD;
    float qreg[HD];
#pragma unroll
    for (int d4 = 0; d4 < HD; d4 += 4) {
        float4 qq = *(const float4*)(qptr + d4);
        qreg[d4 + 0] = qq.x * 0.125f;
        qreg[d4 + 1] = qq.y * 0.125f;
        qreg[d4 + 2] = qq.z * 0.125f;
        qreg[d4 + 3] = qq.w * 0.125f;
    }

    float o[HD];
#pragma unroll
    for (int d = 0; d < HD; d++) o[d] = 0.f;
    float m = -INFINITY, l = 0.f;

    __shared__ float ks[64][HD];
    __shared__ float vs[64][HD];

    int lo = q0 - win + 1;
    if (lo < 0) lo = 0;
    int t0 = lo / 64;
    int t1 = (q0 + 127) / 64;

    for (int t = t0; t <= t1; t++) {
        __syncthreads();
        int base = t * 64;
        // 64 keys x 64 floats = 1024 float4 across 128 threads (8 each)
#pragma unroll
        for (int i = threadIdx.x; i < 64 * 16; i += 128) {
            int r = i >> 4;
            int c4 = (i & 15) * 4;
            size_t off = (((size_t)(b * SS + base + r)) * NKV + kv) * HD + c4;
            *(float4*)&ks[r][c4] = *(const float4*)(g_k + off);
            *(float4*)&vs[r][c4] = *(const float4*)(g_v + off);
        }
        __syncthreads();

        for (int jc = 0; jc < 64; jc += 8) {
            float sbuf[8];
            float cmax = -INFINITY;
#pragma unroll
            for (int j = 0; j < 8; j++) {
                int kpos = base + jc + j;
                float s = -INFINITY;
                if (kpos <= qpos && kpos > qpos - win) {
                    float acc = 0.f;
#pragma unroll
                    for (int d = 0; d < HD; d++) acc += qreg[d] * ks[jc + j][d];
                    s = acc;
                }
                sbuf[j] = s;
                cmax = fmaxf(cmax, s);
            }
            if (cmax == -INFINITY) continue;
            float newm = fmaxf(m, cmax);
            float scale = (m == -INFINITY) ? 0.f : __expf(m - newm);
            m = newm;
            l *= scale;
#pragma unroll
            for (int d = 0; d < HD; d++) o[d] *= scale;
#pragma unroll
            for (int j = 0; j < 8; j++) {
                float p = __expf(sbuf[j] - m);   // -inf -> 0
                l += p;
#pragma unroll
                for (int d = 0; d < HD; d++) o[d] += p * vs[jc + j][d];
            }
        }
    }

    float inv = 1.f / l;    // key==query is always in-window, so l > 0
    float* yp = g_y + (size_t)(b * SS + qpos) * DD + h * HD;
#pragma unroll
    for (int d4 = 0; d4 < HD; d4 += 4) {
        float4 oo = make_float4(o[d4] * inv, o[d4 + 1] * inv,
                                o[d4 + 2] * inv, o[d4 + 3] * inv);
        *(float4*)(yp + d4) = oo;
    }
}

// ---------------------------------------------------------------------------
extern "C" void kernel_launch(void* const* d_in, const int* in_sizes, int n_in,
                              void* d_out, int out_size)
{
    const float* x   = (const float*)d_in[0];
    const float* ve  = (const float*)d_in[1];
    const float* cosp = (const float*)d_in[2];
    const float* sinp = (const float*)d_in[3];
    const float* Wq  = (const float*)d_in[4];
    const float* Wk  = (const float*)d_in[5];
    const float* Wv  = (const float*)d_in[6];
    const float* Wo  = (const float*)d_in[7];
    const float* Wg  = (const float*)d_in[8];
    const int*   win = (const int*)d_in[9];
    float* out = (float*)d_out;

    float *pq, *pk, *pv, *py;
    cudaGetSymbolAddress((void**)&pq, g_q);
    cudaGetSymbolAddress((void**)&pk, g_k);
    cudaGetSymbolAddress((void**)&pv, g_v);
    cudaGetSymbolAddress((void**)&py, g_y);

    const int M = BB * SS;   // 4096

    // QKV projections
    {
        dim3 gq(DD / 64, M / 128);
        sgemm128x64<<<gq, 256>>>(x, Wq, pq, M, DD, DD);
        dim3 gk((NKV * HD) / 64, M / 128);
        sgemm128x64<<<gk, 256>>>(x, Wk, pk, M, NKV * HD, DD);
        sgemm128x64<<<gk, 256>>>(x, Wv, pv, M, NKV * HD, DD);
    }

    // v += gate * ve
    vgate_kernel<<<M, NKV * HD>>>(x, ve, Wg);

    // RoPE + RMSNorm on q and k
    rope_norm_kernel<<<M * (NH + NKV), HD>>>(cosp, sinp);

    // Sliding-window attention
    attn_kernel<<<BB * NH * (SS / 128), 128>>>(win);

    // Output projection
    {
        dim3 go(DD / 64, M / 128);
        sgemm128x64<<<go, 256>>>(py, Wo, out, M, DD, DD);
    }
}

// round 2
// speedup vs baseline: 1.7253x; 1.7253x over previous
#include <cuda_runtime.h>
#include <math.h>
#include <stdint.h>

#define BB 2
#define SS 2048
#define DD 1024
#define NH 16
#define NKV 4
#define HD 64
#define GATE_CH 12
#define EPSV 1e-6f
#define QKVLD 1536   // qkv buffer row stride: [q(1024) | k(256) | v(256)]

// Scratch (allocation-free rule: __device__ globals)
__device__ float g_qkv[BB * SS * QKVLD];   // [b*s][1536]
__device__ float g_y[BB * SS * DD];        // attention output [b*s][1024]

__device__ __forceinline__ float to_tf32(float x) {
    float r;
    asm("cvt.rna.tf32.f32 %0, %1;" : "=f"(r) : "f"(x));
    return r;
}

__device__ __forceinline__ void mma_tf32(float* d, const uint32_t* a, const uint32_t* b) {
    asm volatile(
        "mma.sync.aligned.m16n8k8.row.col.f32.tf32.tf32.f32 "
        "{%0,%1,%2,%3}, {%4,%5,%6,%7}, {%8,%9}, {%0,%1,%2,%3};\n"
        : "+f"(d[0]), "+f"(d[1]), "+f"(d[2]), "+f"(d[3])
        : "r"(a[0]), "r"(a[1]), "r"(a[2]), "r"(a[3]), "r"(b[0]), "r"(b[1]));
}

// ---------------------------------------------------------------------------
// tf32 tensor-core GEMM: C[M,N] = A[M,K] @ W[K,N]  (row-major)
// CTA tile 128x128, BK=16, 256 threads, warp tile 64x32 (2x4 warp grid).
// QKV=1: N-block selects among Wq (cols 0-1023), Wk (1024-1279), Wv (1280-1535).
// ---------------------------------------------------------------------------
template<int QKV>
__global__ __launch_bounds__(256, 2) void gemm_tf32(
    const float* __restrict__ A,
    const float* __restrict__ W0, const float* __restrict__ W1,
    const float* __restrict__ W2,
    float* __restrict__ C, int K, int ldc)
{
    __shared__ float As[128][20];    // [m][k], pad -> frag banks distinct
    __shared__ float Bs[16][136];    // [k][n], pad -> frag banks distinct

    const int tid = threadIdx.x;
    const int lane = tid & 31;
    const int wid = tid >> 5;
    const int gid = lane >> 2;       // 0..7
    const int tig = lane & 3;        // 0..3
    const int warp_m = (wid >> 2) * 64;   // 0 or 64
    const int warp_n = (wid & 3) * 32;    // 0,32,64,96
    const int rowBase = blockIdx.y * 128;
    const int colBase = blockIdx.x * 128;

    const float* W;
    int ldw, wcol;
    if (QKV) {
        if (colBase < 1024)      { W = W0; ldw = 1024; wcol = colBase; }
        else if (colBase < 1280) { W = W1; ldw = 256;  wcol = colBase - 1024; }
        else                     { W = W2; ldw = 256;  wcol = colBase - 1280; }
    } else { W = W0; ldw = ldc; wcol = colBase; }

    float acc[4][4][4] = {};

    for (int k0 = 0; k0 < K; k0 += 16) {
        // A tile: 128x16 = 512 float4, 2 per thread
#pragma unroll
        for (int i = 0; i < 2; i++) {
            int lin = tid + i * 256;
            int r = lin >> 2;
            int c4 = (lin & 3) * 4;
            float4 v = *(const float4*)(A + (size_t)(rowBase + r) * K + k0 + c4);
            v.x = to_tf32(v.x); v.y = to_tf32(v.y);
            v.z = to_tf32(v.z); v.w = to_tf32(v.w);
            *(float4*)&As[r][c4] = v;
        }
        // B tile: 16x128 = 512 float4, 2 per thread
#pragma unroll
        for (int i = 0; i < 2; i++) {
            int lin = tid + i * 256;
            int r = lin >> 5;
            int c4 = (lin & 31) * 4;
            float4 v = *(const float4*)(W + (size_t)(k0 + r) * ldw + wcol + c4);
            v.x = to_tf32(v.x); v.y = to_tf32(v.y);
            v.z = to_tf32(v.z); v.w = to_tf32(v.w);
            *(float4*)&Bs[r][c4] = v;
        }
        __syncthreads();

#pragma unroll
        for (int ks = 0; ks < 16; ks += 8) {
            uint32_t af[4][4], bf[4][2];
#pragma unroll
            for (int mi = 0; mi < 4; mi++) {
                int r0 = warp_m + mi * 16 + gid;
                af[mi][0] = __float_as_uint(As[r0][ks + tig]);
                af[mi][1] = __float_as_uint(As[r0 + 8][ks + tig]);
                af[mi][2] = __float_as_uint(As[r0][ks + tig + 4]);
                af[mi][3] = __float_as_uint(As[r0 + 8][ks + tig + 4]);
            }
#pragma unroll
            for (int ni = 0; ni < 4; ni++) {
                int c0 = warp_n + ni * 8 + gid;
                bf[ni][0] = __float_as_uint(Bs[ks + tig][c0]);
                bf[ni][1] = __float_as_uint(Bs[ks + tig + 4][c0]);
            }
#pragma unroll
            for (int mi = 0; mi < 4; mi++)
#pragma unroll
                for (int ni = 0; ni < 4; ni++)
                    mma_tf32(acc[mi][ni], af[mi], bf[ni]);
        }
        __syncthreads();
    }

#pragma unroll
    for (int mi = 0; mi < 4; mi++) {
#pragma unroll
        for (int ni = 0; ni < 4; ni++) {
            int row = rowBase + warp_m + mi * 16 + gid;
            int col = colBase + warp_n + ni * 8 + 2 * tig;
            *(float2*)(C + (size_t)row * ldc + col) =
                make_float2(acc[mi][ni][0], acc[mi][ni][1]);
            *(float2*)(C + (size_t)(row + 8) * ldc + col) =
                make_float2(acc[mi][ni][2], acc[mi][ni][3]);
        }
    }
}

// ---------------------------------------------------------------------------
// V gate epilogue: v[b,s,kvh,:] += 3*sigmoid(x[b,s,:12] @ Wg[:,kvh]) * ve
// grid = B*S, block = 256 (kvh = t/64, d = t%64)
// ---------------------------------------------------------------------------
__global__ void vgate_kernel(const float* __restrict__ x,
                             const float* __restrict__ ve,
                             const float* __restrict__ Wg)
{
    int bs = blockIdx.x;
    int t = threadIdx.x;
    int kvh = t >> 6;
    const float* xr = x + (size_t)bs * DD;
    float g = 0.f;
#pragma unroll
    for (int c = 0; c < GATE_CH; c++) g += xr[c] * Wg[c * NKV + kvh];
    g = 3.f / (1.f + __expf(-g));
    g_qkv[(size_t)bs * QKVLD + 1280 + t] += g * ve[(size_t)bs * (NKV * HD) + t];
}

// ---------------------------------------------------------------------------
// RoPE + RMSNorm (*1.2) for q and k in place (in qkv buffer).
// grid = B*S*(NH+NKV), block = 64
// ---------------------------------------------------------------------------
__global__ void rope_norm_kernel(const float* __restrict__ cosp,
                                 const float* __restrict__ sinp)
{
    int blk = blockIdx.x;
    int hh = blk % (NH + NKV);
    int bs = blk / (NH + NKV);
    int s = bs % SS;

    float* ptr = g_qkv + (size_t)bs * QKVLD +
                 ((hh < NH) ? hh * HD : 1024 + (hh - NH) * HD);

    int d = threadIdx.x;
    int half = d & 31;
    float c  = cosp[s * 32 + half];
    float sn = sinp[s * 32 + half];
    float x1 = ptr[half];
    float x2 = ptr[half + 32];
    float rot = (d < 32) ? (x1 * c + x2 * sn) : (-x1 * sn + x2 * c);

    __shared__ float red[2];
    float v = rot * rot;
#pragma unroll
    for (int o = 16; o > 0; o >>= 1) v += __shfl_xor_sync(0xffffffffu, v, o);
    if ((d & 31) == 0) red[d >> 5] = v;
    __syncthreads();
    float total = red[0] + red[1];
    float r = rsqrtf(total * (1.f / HD) + EPSV) * 1.2f;
    ptr[d] = rot * r;
}

// ---------------------------------------------------------------------------
// Sliding-window causal attention (fp32, per-thread online softmax).
// grid = B*NH*(S/128), block = 128.
// ---------------------------------------------------------------------------
__global__ __launch_bounds__(128) void attn_kernel(const int* __restrict__ winp)
{
    const int win = *winp;
    int blk = blockIdx.x;
    int qt = blk % (SS / 128);
    int bh = blk / (SS / 128);
    int h = bh % NH;
    int b = bh / NH;
    int q0 = qt * 128;
    int qpos = q0 + threadIdx.x;
    int kv = h / (NH / NKV);

    const float* qptr = g_qkv + (size_t)(b * SS + qpos) * QKVLD + h * HD;
    float qreg[HD];
#pragma unroll
    for (int d4 = 0; d4 < HD; d4 += 4) {
        float4 qq = *(const float4*)(qptr + d4);
        qreg[d4 + 0] = qq.x * 0.125f;
        qreg[d4 + 1] = qq.y * 0.125f;
        qreg[d4 + 2] = qq.z * 0.125f;
        qreg[d4 + 3] = qq.w * 0.125f;
    }

    float o[HD];
#pragma unroll
    for (int d = 0; d < HD; d++) o[d] = 0.f;
    float m = -INFINITY, l = 0.f;

    __shared__ float ks[64][HD];
    __shared__ float vs[64][HD];

    int lo = q0 - win + 1;
    if (lo < 0) lo = 0;
    int t0 = lo / 64;
    int t1 = (q0 + 127) / 64;

    for (int t = t0; t <= t1; t++) {
        __syncthreads();
        int base = t * 64;
#pragma unroll
        for (int i = threadIdx.x; i < 64 * 16; i += 128) {
            int r = i >> 4;
            int c4 = (i & 15) * 4;
            size_t off = (size_t)(b * SS + base + r) * QKVLD + kv * HD + c4;
            *(float4*)&ks[r][c4] = *(const float4*)(g_qkv + off + 1024);
            *(float4*)&vs[r][c4] = *(const float4*)(g_qkv + off + 1280);
        }
        __syncthreads();

        for (int jc = 0; jc < 64; jc += 8) {
            float sbuf[8];
            float cmax = -INFINITY;
#pragma unroll
            for (int j = 0; j < 8; j++) {
                int kpos = base + jc + j;
                float s = -INFINITY;
                if (kpos <= qpos && kpos > qpos - win) {
                    float a2 = 0.f;
#pragma unroll
                    for (int d = 0; d < HD; d++) a2 += qreg[d] * ks[jc + j][d];
                    s = a2;
                }
                sbuf[j] = s;
                cmax = fmaxf(cmax, s);
            }
            if (cmax == -INFINITY) continue;
            float newm = fmaxf(m, cmax);
            float scale = (m == -INFINITY) ? 0.f : __expf(m - newm);
            m = newm;
            l *= scale;
#pragma unroll
            for (int d = 0; d < HD; d++) o[d] *= scale;
#pragma unroll
            for (int j = 0; j < 8; j++) {
                float p = __expf(sbuf[j] - m);
                l += p;
#pragma unroll
                for (int d = 0; d < HD; d++) o[d] += p * vs[jc + j][d];
            }
        }
    }

    float inv = 1.f / l;
    float* yp = g_y + (size_t)(b * SS + qpos) * DD + h * HD;
#pragma unroll
    for (int d4 = 0; d4 < HD; d4 += 4) {
        float4 oo = make_float4(o[d4] * inv, o[d4 + 1] * inv,
                                o[d4 + 2] * inv, o[d4 + 3] * inv);
        *(float4*)(yp + d4) = oo;
    }
}

// ---------------------------------------------------------------------------
extern "C" void kernel_launch(void* const* d_in, const int* in_sizes, int n_in,
                              void* d_out, int out_size)
{
    const float* x    = (const float*)d_in[0];
    const float* ve   = (const float*)d_in[1];
    const float* cosp = (const float*)d_in[2];
    const float* sinp = (const float*)d_in[3];
    const float* Wq   = (const float*)d_in[4];
    const float* Wk   = (const float*)d_in[5];
    const float* Wv   = (const float*)d_in[6];
    const float* Wo   = (const float*)d_in[7];
    const float* Wg   = (const float*)d_in[8];
    const int*   win  = (const int*)d_in[9];
    float* out = (float*)d_out;

    float *pqkv, *py;
    cudaGetSymbolAddress((void**)&pqkv, g_qkv);
    cudaGetSymbolAddress((void**)&py, g_y);

    const int M = BB * SS;   // 4096

    // Fused QKV projection (tf32 tensor cores)
    {
        dim3 g(QKVLD / 128, M / 128);
        gemm_tf32<1><<<g, 256>>>(x, Wq, Wk, Wv, pqkv, DD, QKVLD);
    }

    // v += gate * ve
    vgate_kernel<<<M, NKV * HD>>>(x, ve, Wg);

    // RoPE + RMSNorm on q and k
    rope_norm_kernel<<<M * (NH + NKV), HD>>>(cosp, sinp);

    // Sliding-window attention
    attn_kernel<<<BB * NH * (SS / 128), 128>>>(win);

    // Output projection (tf32 tensor cores)
    {
        dim3 g(DD / 128, M / 128);
        gemm_tf32<0><<<g, 256>>>(py, Wo, nullptr, nullptr, out, DD, DD);
    }
}

// round 3
// speedup vs baseline: 2.5830x; 1.4971x over previous
#include <cuda_runtime.h>
#include <math.h>
#include <stdint.h>

#define BB 2
#define SS 2048
#define DD 1024
#define NH 16
#define NKV 4
#define HD 64
#define GATE_CH 12
#define EPSV 1e-6f
#define QKVLD 1536   // qkv buffer row stride: [q(1024) | k(256) | v(256)]

// Scratch (allocation-free rule: __device__ globals)
__device__ float g_qkv[BB * SS * QKVLD];   // [b*s][1536]
__device__ float g_y[BB * SS * DD];        // attention output [b*s][1024]

__device__ __forceinline__ float to_tf32(float x) {
    float r;
    asm("cvt.rna.tf32.f32 %0, %1;" : "=f"(r) : "f"(x));
    return r;
}
__device__ __forceinline__ uint32_t tf32u(float x) {
    float r;
    asm("cvt.rna.tf32.f32 %0, %1;" : "=f"(r) : "f"(x));
    return __float_as_uint(r);
}

__device__ __forceinline__ void mma_tf32(float* d, const uint32_t* a, const uint32_t* b) {
    asm volatile(
        "mma.sync.aligned.m16n8k8.row.col.f32.tf32.tf32.f32 "
        "{%0,%1,%2,%3}, {%4,%5,%6,%7}, {%8,%9}, {%0,%1,%2,%3};\n"
        : "+f"(d[0]), "+f"(d[1]), "+f"(d[2]), "+f"(d[3])
        : "r"(a[0]), "r"(a[1]), "r"(a[2]), "r"(a[3]), "r"(b[0]), "r"(b[1]));
}

// ---------------------------------------------------------------------------
// tf32 tensor-core GEMM: C[M,N] = A[M,K] @ W[K,N]  (row-major)
// CTA tile 128x128, BK=16, 256 threads, warp tile 64x32 (2x4 warp grid).
// ---------------------------------------------------------------------------
template<int QKV>
__global__ __launch_bounds__(256, 2) void gemm_tf32(
    const float* __restrict__ A,
    const float* __restrict__ W0, const float* __restrict__ W1,
    const float* __restrict__ W2,
    float* __restrict__ C, int K, int ldc)
{
    __shared__ float As[128][20];
    __shared__ float Bs[16][136];

    const int tid = threadIdx.x;
    const int lane = tid & 31;
    const int wid = tid >> 5;
    const int gid = lane >> 2;
    const int tig = lane & 3;
    const int warp_m = (wid >> 2) * 64;
    const int warp_n = (wid & 3) * 32;
    const int rowBase = blockIdx.y * 128;
    const int colBase = blockIdx.x * 128;

    const float* W;
    int ldw, wcol;
    if (QKV) {
        if (colBase < 1024)      { W = W0; ldw = 1024; wcol = colBase; }
        else if (colBase < 1280) { W = W1; ldw = 256;  wcol = colBase - 1024; }
        else                     { W = W2; ldw = 256;  wcol = colBase - 1280; }
    } else { W = W0; ldw = ldc; wcol = colBase; }

    float acc[4][4][4] = {};

    for (int k0 = 0; k0 < K; k0 += 16) {
#pragma unroll
        for (int i = 0; i < 2; i++) {
            int lin = tid + i * 256;
            int r = lin >> 2;
            int c4 = (lin & 3) * 4;
            float4 v = *(const float4*)(A + (size_t)(rowBase + r) * K + k0 + c4);
            v.x = to_tf32(v.x); v.y = to_tf32(v.y);
            v.z = to_tf32(v.z); v.w = to_tf32(v.w);
            *(float4*)&As[r][c4] = v;
        }
#pragma unroll
        for (int i = 0; i < 2; i++) {
            int lin = tid + i * 256;
            int r = lin >> 5;
            int c4 = (lin & 31) * 4;
            float4 v = *(const float4*)(W + (size_t)(k0 + r) * ldw + wcol + c4);
            v.x = to_tf32(v.x); v.y = to_tf32(v.y);
            v.z = to_tf32(v.z); v.w = to_tf32(v.w);
            *(float4*)&Bs[r][c4] = v;
        }
        __syncthreads();

#pragma unroll
        for (int ks = 0; ks < 16; ks += 8) {
            uint32_t af[4][4], bf[4][2];
#pragma unroll
            for (int mi = 0; mi < 4; mi++) {
                int r0 = warp_m + mi * 16 + gid;
                af[mi][0] = __float_as_uint(As[r0][ks + tig]);
                af[mi][1] = __float_as_uint(As[r0 + 8][ks + tig]);
                af[mi][2] = __float_as_uint(As[r0][ks + tig + 4]);
                af[mi][3] = __float_as_uint(As[r0 + 8][ks + tig + 4]);
            }
#pragma unroll
            for (int ni = 0; ni < 4; ni++) {
                int c0 = warp_n + ni * 8 + gid;
                bf[ni][0] = __float_as_uint(Bs[ks + tig][c0]);
                bf[ni][1] = __float_as_uint(Bs[ks + tig + 4][c0]);
            }
#pragma unroll
            for (int mi = 0; mi < 4; mi++)
#pragma unroll
                for (int ni = 0; ni < 4; ni++)
                    mma_tf32(acc[mi][ni], af[mi], bf[ni]);
        }
        __syncthreads();
    }

#pragma unroll
    for (int mi = 0; mi < 4; mi++) {
#pragma unroll
        for (int ni = 0; ni < 4; ni++) {
            int row = rowBase + warp_m + mi * 16 + gid;
            int col = colBase + warp_n + ni * 8 + 2 * tig;
            *(float2*)(C + (size_t)row * ldc + col) =
                make_float2(acc[mi][ni][0], acc[mi][ni][1]);
            *(float2*)(C + (size_t)(row + 8) * ldc + col) =
                make_float2(acc[mi][ni][2], acc[mi][ni][3]);
        }
    }
}

// ---------------------------------------------------------------------------
// V gate epilogue
// ---------------------------------------------------------------------------
__global__ void vgate_kernel(const float* __restrict__ x,
                             const float* __restrict__ ve,
                             const float* __restrict__ Wg)
{
    int bs = blockIdx.x;
    int t = threadIdx.x;
    int kvh = t >> 6;
    const float* xr = x + (size_t)bs * DD;
    float g = 0.f;
#pragma unroll
    for (int c = 0; c < GATE_CH; c++) g += xr[c] * Wg[c * NKV + kvh];
    g = 3.f / (1.f + __expf(-g));
    g_qkv[(size_t)bs * QKVLD + 1280 + t] += g * ve[(size_t)bs * (NKV * HD) + t];
}

// ---------------------------------------------------------------------------
// RoPE + RMSNorm (*1.2) for q and k in place (in qkv buffer).
// ---------------------------------------------------------------------------
__global__ void rope_norm_kernel(const float* __restrict__ cosp,
                                 const float* __restrict__ sinp)
{
    int blk = blockIdx.x;
    int hh = blk % (NH + NKV);
    int bs = blk / (NH + NKV);
    int s = bs % SS;

    float* ptr = g_qkv + (size_t)bs * QKVLD +
                 ((hh < NH) ? hh * HD : 1024 + (hh - NH) * HD);

    int d = threadIdx.x;
    int half = d & 31;
    float c  = cosp[s * 32 + half];
    float sn = sinp[s * 32 + half];
    float x1 = ptr[half];
    float x2 = ptr[half + 32];
    float rot = (d < 32) ? (x1 * c + x2 * sn) : (-x1 * sn + x2 * c);

    __shared__ float red[2];
    float v = rot * rot;
#pragma unroll
    for (int o = 16; o > 0; o >>= 1) v += __shfl_xor_sync(0xffffffffu, v, o);
    if ((d & 31) == 0) red[d >> 5] = v;
    __syncthreads();
    float total = red[0] + red[1];
    float r = rsqrtf(total * (1.f / HD) + EPSV) * 1.2f;
    ptr[d] = rot * r;
}

// ---------------------------------------------------------------------------
// Tensor-core flash attention (tf32, hi/lo-compensated QK^T).
// grid = B*NH*(S/64), block = 128 (4 warps; warp w owns query rows 16w..16w+15).
// Dynamic smem: Ks[64][68] | Vs[64][68] | Ss[64][68] | scb[64] | lbuf[64]
// ---------------------------------------------------------------------------
#define ATS 68   // smem row stride
__global__ __launch_bounds__(128) void attn_tc(const int* __restrict__ winp)
{
    const int win = *winp;
    int bid = blockIdx.x;
    int qt = bid & 31;
    int bh = bid >> 5;
    int h = bh % NH;
    int b = bh / NH;
    int q0 = qt * 64;
    int kvh = h / (NH / NKV);

    const int tid = threadIdx.x;
    const int lane = tid & 31;
    const int warp = tid >> 5;
    const int wrow = warp * 16;
    const int gid = lane >> 2;
    const int tig = lane & 3;

    extern __shared__ float sm[];
    float* Ks = sm;
    float* Vs = sm + 64 * ATS;
    float* Ss = sm + 2 * 64 * ATS;
    float* scb  = sm + 3 * 64 * ATS;
    float* lbuf = scb + 64;

    // ---- stage Q tile into Ss, then pull hi/lo fragments into registers ----
    for (int i = tid; i < 64 * 16; i += 128) {
        int r = i >> 4;
        int c4 = (i & 15) * 4;
        *(float4*)&Ss[r * ATS + c4] =
            *(const float4*)(g_qkv + (size_t)(b * SS + q0 + r) * QKVLD + h * HD + c4);
    }
    __syncthreads();

    uint32_t ahi[8][4], alo[8][4];
#pragma unroll
    for (int ks = 0; ks < 8; ks++) {
#pragma unroll
        for (int idx = 0; idx < 4; idx++) {
            int row = wrow + gid + ((idx & 1) << 3);
            int col = ks * 8 + tig + ((idx >> 1) << 2);
            float v = Ss[row * ATS + col] * 0.125f;
            float hi = to_tf32(v);
            ahi[ks][idx] = __float_as_uint(hi);
            alo[ks][idx] = tf32u(v - hi);
        }
    }

    float m = -1e30f, lsum = 0.f;
    float oacc[8][4] = {};

    int kmin = q0 - win + 1;
    if (kmin < 0) kmin = 0;
    int t0 = kmin >> 6;
    int t1 = (q0 + 63) >> 6;

    for (int t = t0; t <= t1; t++) {
        int kb = t << 6;
        __syncthreads();   // prior-iteration Vs/Ss reads done before overwrite
        for (int i = tid; i < 64 * 16; i += 128) {
            int r = i >> 4;
            int c4 = (i & 15) * 4;
            const float* kp = g_qkv + (size_t)(b * SS + kb + r) * QKVLD + 1024 + kvh * HD + c4;
            *(float4*)&Ks[r * ATS + c4] = *(const float4*)kp;
            *(float4*)&Vs[r * ATS + c4] = *(const float4*)(kp + 256);
        }
        __syncthreads();

        // ---- S = Q @ K^T (hi/lo compensated) ----
        float accS[8][4] = {};
#pragma unroll
        for (int ks = 0; ks < 8; ks++) {
#pragma unroll
            for (int ni = 0; ni < 8; ni++) {
                const float* kr = &Ks[(ni * 8 + gid) * ATS + ks * 8 + tig];
                float k0 = kr[0], k1 = kr[4];
                float h0 = to_tf32(k0), h1 = to_tf32(k1);
                uint32_t bhi[2] = { __float_as_uint(h0), __float_as_uint(h1) };
                uint32_t blo[2] = { tf32u(k0 - h0), tf32u(k1 - h1) };
                mma_tf32(accS[ni], ahi[ks], bhi);
                mma_tf32(accS[ni], alo[ks], bhi);
                mma_tf32(accS[ni], ahi[ks], blo);
            }
        }

        // ---- write masked S to smem (warp-private rows) ----
#pragma unroll
        for (int ni = 0; ni < 8; ni++) {
#pragma unroll
            for (int j = 0; j < 4; j++) {
                int col = ni * 8 + 2 * tig + (j & 1);
                int r = gid + ((j >> 1) << 3);
                int qpos = q0 + wrow + r;
                int kpos = kb + col;
                bool ok = (kpos <= qpos) && (kpos >= qpos - win + 1);
                Ss[(wrow + r) * ATS + col] = ok ? accS[ni][j] : -1e30f;
            }
        }
        __syncwarp();

        // ---- online softmax: 2 lanes per row, 32 cols each ----
        {
            int srow = lane >> 1;
            int cb = (lane & 1) * 32;
            float* sp = &Ss[(wrow + srow) * ATS + cb];
            float rmax = -1e30f;
#pragma unroll
            for (int c = 0; c < 32; c++) rmax = fmaxf(rmax, sp[c]);
            rmax = fmaxf(rmax, __shfl_xor_sync(0xffffffffu, rmax, 1));
            float mnew = fmaxf(m, rmax);
            float scale, rs = 0.f;
            if (mnew <= -1e20f) {            // row has seen no valid key yet
                scale = 1.f;
#pragma unroll
                for (int c = 0; c < 32; c++) sp[c] = 0.f;
            } else {
                scale = __expf(m - mnew);
#pragma unroll
                for (int c = 0; c < 32; c++) {
                    float p = __expf(sp[c] - mnew);
                    sp[c] = p;
                    rs += p;
                }
            }
            m = mnew;
            rs += __shfl_xor_sync(0xffffffffu, rs, 1);
            lsum = lsum * scale + rs;
            if ((lane & 1) == 0) scb[wrow + srow] = scale;
        }
        __syncwarp();

        // ---- rescale O, then O += P @ V ----
        {
            float sc0 = scb[wrow + gid];
            float sc1 = scb[wrow + gid + 8];
#pragma unroll
            for (int ni = 0; ni < 8; ni++) {
                oacc[ni][0] *= sc0; oacc[ni][1] *= sc0;
                oacc[ni][2] *= sc1; oacc[ni][3] *= sc1;
            }
        }
#pragma unroll
        for (int ks = 0; ks < 8; ks++) {
            uint32_t pa[4];
            pa[0] = tf32u(Ss[(wrow + gid) * ATS + ks * 8 + tig]);
            pa[1] = tf32u(Ss[(wrow + gid + 8) * ATS + ks * 8 + tig]);
            pa[2] = tf32u(Ss[(wrow + gid) * ATS + ks * 8 + tig + 4]);
            pa[3] = tf32u(Ss[(wrow + gid + 8) * ATS + ks * 8 + tig + 4]);
#pragma unroll
            for (int ni = 0; ni < 8; ni++) {
                uint32_t vb[2];
                vb[0] = tf32u(Vs[(ks * 8 + tig) * ATS + ni * 8 + gid]);
                vb[1] = tf32u(Vs[(ks * 8 + tig + 4) * ATS + ni * 8 + gid]);
                mma_tf32(oacc[ni], pa, vb);
            }
        }
    }

    // ---- normalize and write out ----
    if ((lane & 1) == 0) lbuf[wrow + (lane >> 1)] = lsum;
    __syncwarp();
    float li0 = 1.f / lbuf[wrow + gid];
    float li1 = 1.f / lbuf[wrow + gid + 8];

#pragma unroll
    for (int ni = 0; ni < 8; ni++) {
        int col = h * HD + ni * 8 + 2 * tig;
        int row0 = b * SS + q0 + wrow + gid;
        *(float2*)(g_y + (size_t)row0 * DD + col) =
            make_float2(oacc[ni][0] * li0, oacc[ni][1] * li0);
        *(float2*)(g_y + (size_t)(row0 + 8) * DD + col) =
            make_float2(oacc[ni][2] * li1, oacc[ni][3] * li1);
    }
}

// ---------------------------------------------------------------------------
extern "C" void kernel_launch(void* const* d_in, const int* in_sizes, int n_in,
                              void* d_out, int out_size)
{
    const float* x    = (const float*)d_in[0];
    const float* ve   = (const float*)d_in[1];
    const float* cosp = (const float*)d_in[2];
    const float* sinp = (const float*)d_in[3];
    const float* Wq   = (const float*)d_in[4];
    const float* Wk   = (const float*)d_in[5];
    const float* Wv   = (const float*)d_in[6];
    const float* Wo   = (const float*)d_in[7];
    const float* Wg   = (const float*)d_in[8];
    const int*   win  = (const int*)d_in[9];
    float* out = (float*)d_out;

    float *pqkv, *py;
    cudaGetSymbolAddress((void**)&pqkv, g_qkv);
    cudaGetSymbolAddress((void**)&py, g_y);

    const int M = BB * SS;   // 4096

    // Fused QKV projection (tf32 tensor cores)
    {
        dim3 g(QKVLD / 128, M / 128);
        gemm_tf32<1><<<g, 256>>>(x, Wq, Wk, Wv, pqkv, DD, QKVLD);
    }

    vgate_kernel<<<M, NKV * HD>>>(x, ve, Wg);
    rope_norm_kernel<<<M * (NH + NKV), HD>>>(cosp, sinp);

    // Tensor-core flash attention
    {
        int smem = (3 * 64 * ATS + 128) * sizeof(float);   // 52736 B
        cudaFuncSetAttribute(attn_tc, cudaFuncAttributeMaxDynamicSharedMemorySize, smem);
        attn_tc<<<BB * NH * (SS / 64), 128, smem>>>(win);
    }

    // Output projection (tf32 tensor cores)
    {
        dim3 g(DD / 128, M / 128);
        gemm_tf32<0><<<g, 256>>>(py, Wo, nullptr, nullptr, out, DD, DD);
    }
}

// round 4
// speedup vs baseline: 2.6353x; 1.0203x over previous
#include <cuda_runtime.h>
#include <math.h>
#include <stdint.h>

#define BB 2
#define SS 2048
#define DD 1024
#define NH 16
#define NKV 4
#define HD 64
#define GATE_CH 12
#define EPSV 1e-6f
#define QKVLD 1536   // qkv buffer row stride: [q(1024) | k(256) | v(256)]

// Scratch (allocation-free rule: __device__ globals)
__device__ float g_qkv[BB * SS * QKVLD];   // [b*s][1536]
__device__ float g_y[BB * SS * DD];        // attention output [b*s][1024]

__device__ __forceinline__ float to_tf32(float x) {
    float r;
    asm("cvt.rna.tf32.f32 %0, %1;" : "=f"(r) : "f"(x));
    return r;
}
__device__ __forceinline__ uint32_t tf32u(float x) {
    float r;
    asm("cvt.rna.tf32.f32 %0, %1;" : "=f"(r) : "f"(x));
    return __float_as_uint(r);
}

__device__ __forceinline__ void mma_tf32(float* d, const uint32_t* a, const uint32_t* b) {
    asm volatile(
        "mma.sync.aligned.m16n8k8.row.col.f32.tf32.tf32.f32 "
        "{%0,%1,%2,%3}, {%4,%5,%6,%7}, {%8,%9}, {%0,%1,%2,%3};\n"
        : "+f"(d[0]), "+f"(d[1]), "+f"(d[2]), "+f"(d[3])
        : "r"(a[0]), "r"(a[1]), "r"(a[2]), "r"(a[3]), "r"(b[0]), "r"(b[1]));
}

// ---------------------------------------------------------------------------
// tf32 tensor-core GEMM, 2-stage pipelined: C[M,N] = A[M,K] @ W[K,N]
// CTA tile 128x128, BK=16, 256 threads, warp tile 64x32 (2x4 warp grid).
// ---------------------------------------------------------------------------
template<int QKV>
__global__ __launch_bounds__(256, 2) void gemm_tf32(
    const float* __restrict__ A,
    const float* __restrict__ W0, const float* __restrict__ W1,
    const float* __restrict__ W2,
    float* __restrict__ C, int K, int ldc)
{
    __shared__ float As[2][128][20];
    __shared__ float Bs[2][16][136];

    const int tid = threadIdx.x;
    const int lane = tid & 31;
    const int wid = tid >> 5;
    const int gid = lane >> 2;
    const int tig = lane & 3;
    const int warp_m = (wid >> 2) * 64;
    const int warp_n = (wid & 3) * 32;
    const int rowBase = blockIdx.y * 128;
    const int colBase = blockIdx.x * 128;

    const float* W;
    int ldw, wcol;
    if (QKV) {
        if (colBase < 1024)      { W = W0; ldw = 1024; wcol = colBase; }
        else if (colBase < 1280) { W = W1; ldw = 256;  wcol = colBase - 1024; }
        else                     { W = W2; ldw = 256;  wcol = colBase - 1280; }
    } else { W = W0; ldw = ldc; wcol = colBase; }

    // per-thread load coordinates
    const int a_r0 = tid >> 2;            const int a_c0 = (tid & 3) * 4;
    const int a_r1 = (tid + 256) >> 2;    const int a_c1 = a_c0;
    const int b_r0 = tid >> 5;            const int b_c0 = (tid & 31) * 4;
    const int b_r1 = (tid + 256) >> 5;    const int b_c1 = b_c0;

    const float* Abase0 = A + (size_t)(rowBase + a_r0) * K + a_c0;
    const float* Abase1 = A + (size_t)(rowBase + a_r1) * K + a_c1;
    const float* Wbase0 = W + (size_t)b_r0 * ldw + wcol + b_c0;
    const float* Wbase1 = W + (size_t)b_r1 * ldw + wcol + b_c1;

    float acc[4][4][4] = {};
    float4 ra0, ra1, rb0, rb1;

    // prologue: load tile 0, convert, store stage 0
    ra0 = *(const float4*)Abase0;
    ra1 = *(const float4*)Abase1;
    rb0 = *(const float4*)Wbase0;
    rb1 = *(const float4*)Wbase1;
    {
        float4 t;
        t = ra0; t.x=to_tf32(t.x); t.y=to_tf32(t.y); t.z=to_tf32(t.z); t.w=to_tf32(t.w);
        *(float4*)&As[0][a_r0][a_c0] = t;
        t = ra1; t.x=to_tf32(t.x); t.y=to_tf32(t.y); t.z=to_tf32(t.z); t.w=to_tf32(t.w);
        *(float4*)&As[0][a_r1][a_c1] = t;
        t = rb0; t.x=to_tf32(t.x); t.y=to_tf32(t.y); t.z=to_tf32(t.z); t.w=to_tf32(t.w);
        *(float4*)&Bs[0][b_r0][b_c0] = t;
        t = rb1; t.x=to_tf32(t.x); t.y=to_tf32(t.y); t.z=to_tf32(t.z); t.w=to_tf32(t.w);
        *(float4*)&Bs[0][b_r1][b_c1] = t;
    }
    __syncthreads();

    const int iters = K / 16;
    for (int it = 0; it < iters; it++) {
        const int s = it & 1;
        const bool more = (it + 1) < iters;
        if (more) {
            int k0n = (it + 1) * 16;
            ra0 = *(const float4*)(Abase0 + k0n);
            ra1 = *(const float4*)(Abase1 + k0n);
            rb0 = *(const float4*)(Wbase0 + (size_t)k0n * ldw);
            rb1 = *(const float4*)(Wbase1 + (size_t)k0n * ldw);
        }

#pragma unroll
        for (int ks = 0; ks < 16; ks += 8) {
            uint32_t af[4][4], bf[4][2];
#pragma unroll
            for (int mi = 0; mi < 4; mi++) {
                int r0 = warp_m + mi * 16 + gid;
                af[mi][0] = __float_as_uint(As[s][r0][ks + tig]);
                af[mi][1] = __float_as_uint(As[s][r0 + 8][ks + tig]);
                af[mi][2] = __float_as_uint(As[s][r0][ks + tig + 4]);
                af[mi][3] = __float_as_uint(As[s][r0 + 8][ks + tig + 4]);
            }
#pragma unroll
            for (int ni = 0; ni < 4; ni++) {
                int c0 = warp_n + ni * 8 + gid;
                bf[ni][0] = __float_as_uint(Bs[s][ks + tig][c0]);
                bf[ni][1] = __float_as_uint(Bs[s][ks + tig + 4][c0]);
            }
#pragma unroll
            for (int mi = 0; mi < 4; mi++)
#pragma unroll
                for (int ni = 0; ni < 4; ni++)
                    mma_tf32(acc[mi][ni], af[mi], bf[ni]);
        }

        if (more) {
            const int d = s ^ 1;
            float4 t;
            t = ra0; t.x=to_tf32(t.x); t.y=to_tf32(t.y); t.z=to_tf32(t.z); t.w=to_tf32(t.w);
            *(float4*)&As[d][a_r0][a_c0] = t;
            t = ra1; t.x=to_tf32(t.x); t.y=to_tf32(t.y); t.z=to_tf32(t.z); t.w=to_tf32(t.w);
            *(float4*)&As[d][a_r1][a_c1] = t;
            t = rb0; t.x=to_tf32(t.x); t.y=to_tf32(t.y); t.z=to_tf32(t.z); t.w=to_tf32(t.w);
            *(float4*)&Bs[d][b_r0][b_c0] = t;
            t = rb1; t.x=to_tf32(t.x); t.y=to_tf32(t.y); t.z=to_tf32(t.z); t.w=to_tf32(t.w);
            *(float4*)&Bs[d][b_r1][b_c1] = t;
        }
        __syncthreads();
    }

#pragma unroll
    for (int mi = 0; mi < 4; mi++) {
#pragma unroll
        for (int ni = 0; ni < 4; ni++) {
            int row = rowBase + warp_m + mi * 16 + gid;
            int col = colBase + warp_n + ni * 8 + 2 * tig;
            *(float2*)(C + (size_t)row * ldc + col) =
                make_float2(acc[mi][ni][0], acc[mi][ni][1]);
            *(float2*)(C + (size_t)(row + 8) * ldc + col) =
                make_float2(acc[mi][ni][2], acc[mi][ni][3]);
        }
    }
}

// ---------------------------------------------------------------------------
// V gate epilogue
// ---------------------------------------------------------------------------
__global__ void vgate_kernel(const float* __restrict__ x,
                             const float* __restrict__ ve,
                             const float* __restrict__ Wg)
{
    int bs = blockIdx.x;
    int t = threadIdx.x;
    int kvh = t >> 6;
    const float* xr = x + (size_t)bs * DD;
    float g = 0.f;
#pragma unroll
    for (int c = 0; c < GATE_CH; c++) g += xr[c] * Wg[c * NKV + kvh];
    g = 3.f / (1.f + __expf(-g));
    g_qkv[(size_t)bs * QKVLD + 1280 + t] += g * ve[(size_t)bs * (NKV * HD) + t];
}

// ---------------------------------------------------------------------------
// RoPE + RMSNorm (*1.2) for q and k in place (in qkv buffer).
// ---------------------------------------------------------------------------
__global__ void rope_norm_kernel(const float* __restrict__ cosp,
                                 const float* __restrict__ sinp)
{
    int blk = blockIdx.x;
    int hh = blk % (NH + NKV);
    int bs = blk / (NH + NKV);
    int s = bs % SS;

    float* ptr = g_qkv + (size_t)bs * QKVLD +
                 ((hh < NH) ? hh * HD : 1024 + (hh - NH) * HD);

    int d = threadIdx.x;
    int half = d & 31;
    float c  = cosp[s * 32 + half];
    float sn = sinp[s * 32 + half];
    float x1 = ptr[half];
    float x2 = ptr[half + 32];
    float rot = (d < 32) ? (x1 * c + x2 * sn) : (-x1 * sn + x2 * c);

    __shared__ float red[2];
    float v = rot * rot;
#pragma unroll
    for (int o = 16; o > 0; o >>= 1) v += __shfl_xor_sync(0xffffffffu, v, o);
    if ((d & 31) == 0) red[d >> 5] = v;
    __syncthreads();
    float total = red[0] + red[1];
    float r = rsqrtf(total * (1.f / HD) + EPSV) * 1.2f;
    ptr[d] = rot * r;
}

// ---------------------------------------------------------------------------
// Tensor-core flash attention (tf32, hi/lo-compensated QK^T).
// grid = B*NH*(S/64), block = 128 (4 warps; warp w owns query rows 16w..16w+15).
// smem: Ks(hi)[64][68] | Klo[64][68] | Vt[64][68] (transposed, tf32) |
//       Ss[64][68] | scb[64] | lbuf[64]
// All tf32 conversion hoisted to tile-staging time.
// ---------------------------------------------------------------------------
#define ATS 68   // smem row stride
__global__ __launch_bounds__(128) void attn_tc(const int* __restrict__ winp)
{
    const int win = *winp;
    int bid = blockIdx.x;
    int qt = bid & 31;
    int bh = bid >> 5;
    int h = bh % NH;
    int b = bh / NH;
    int q0 = qt * 64;
    int kvh = h / (NH / NKV);

    const int tid = threadIdx.x;
    const int lane = tid & 31;
    const int warp = tid >> 5;
    const int wrow = warp * 16;
    const int gid = lane >> 2;
    const int tig = lane & 3;

    extern __shared__ float sm[];
    float* Ks  = sm;                   // K hi (tf32)
    float* Klo = sm + 64 * ATS;        // K lo (tf32 of residual)
    float* Vt  = sm + 2 * 64 * ATS;    // V transposed [d][key], tf32
    float* Ss  = sm + 3 * 64 * ATS;
    float* scb  = sm + 4 * 64 * ATS;
    float* lbuf = scb + 64;

    // ---- stage Q tile into Ss, then pull hi/lo fragments into registers ----
    for (int i = tid; i < 64 * 16; i += 128) {
        int r = i >> 4;
        int c4 = (i & 15) * 4;
        *(float4*)&Ss[r * ATS + c4] =
            *(const float4*)(g_qkv + (size_t)(b * SS + q0 + r) * QKVLD + h * HD + c4);
    }
    __syncthreads();

    uint32_t ahi[8][4], alo[8][4];
#pragma unroll
    for (int ks = 0; ks < 8; ks++) {
#pragma unroll
        for (int idx = 0; idx < 4; idx++) {
            int row = wrow + gid + ((idx & 1) << 3);
            int col = ks * 8 + tig + ((idx >> 1) << 2);
            float v = Ss[row * ATS + col] * 0.125f;
            float hi = to_tf32(v);
            ahi[ks][idx] = __float_as_uint(hi);
            alo[ks][idx] = tf32u(v - hi);
        }
    }

    float m = -1e30f, lsum = 0.f;
    float oacc[8][4] = {};

    int kmin = q0 - win + 1;
    if (kmin < 0) kmin = 0;
    int t0 = kmin >> 6;
    int t1 = (q0 + 63) >> 6;

    for (int t = t0; t <= t1; t++) {
        int kb = t << 6;
        __syncthreads();   // prior-iteration reads done before overwrite
        // ---- stage K (hi/lo split) and V (transposed), all pre-converted ----
        for (int i = tid; i < 64 * 16; i += 128) {
            int r = i >> 4;
            int c4 = (i & 15) * 4;
            const float* kp = g_qkv + (size_t)(b * SS + kb + r) * QKVLD + 1024 + kvh * HD + c4;
            float4 kk = *(const float4*)kp;
            float4 hi, lo;
            hi.x = to_tf32(kk.x); lo.x = to_tf32(kk.x - hi.x);
            hi.y = to_tf32(kk.y); lo.y = to_tf32(kk.y - hi.y);
            hi.z = to_tf32(kk.z); lo.z = to_tf32(kk.z - hi.z);
            hi.w = to_tf32(kk.w); lo.w = to_tf32(kk.w - hi.w);
            *(float4*)&Ks[r * ATS + c4]  = hi;
            *(float4*)&Klo[r * ATS + c4] = lo;
            float4 vv = *(const float4*)(kp + 256);
            Vt[(c4 + 0) * ATS + r] = to_tf32(vv.x);
            Vt[(c4 + 1) * ATS + r] = to_tf32(vv.y);
            Vt[(c4 + 2) * ATS + r] = to_tf32(vv.z);
            Vt[(c4 + 3) * ATS + r] = to_tf32(vv.w);
        }
        __syncthreads();

        // ---- S = Q @ K^T (hi/lo compensated), pure LDS + MMA ----
        float accS[8][4] = {};
#pragma unroll
        for (int ks = 0; ks < 8; ks++) {
#pragma unroll
            for (int ni = 0; ni < 8; ni++) {
                const float* kr  = &Ks[(ni * 8 + gid) * ATS + ks * 8 + tig];
                const float* klr = &Klo[(ni * 8 + gid) * ATS + ks * 8 + tig];
                uint32_t bhi[2] = { __float_as_uint(kr[0]),  __float_as_uint(kr[4]) };
                uint32_t blo[2] = { __float_as_uint(klr[0]), __float_as_uint(klr[4]) };
                mma_tf32(accS[ni], ahi[ks], bhi);
                mma_tf32(accS[ni], alo[ks], bhi);
                mma_tf32(accS[ni], ahi[ks], blo);
            }
        }

        // ---- write masked S to smem (warp-private rows) ----
#pragma unroll
        for (int ni = 0; ni < 8; ni++) {
#pragma unroll
            for (int j = 0; j < 4; j++) {
                int col = ni * 8 + 2 * tig + (j & 1);
                int r = gid + ((j >> 1) << 3);
                int qpos = q0 + wrow + r;
                int kpos = kb + col;
                bool ok = (kpos <= qpos) && (kpos >= qpos - win + 1);
                Ss[(wrow + r) * ATS + col] = ok ? accS[ni][j] : -1e30f;
            }
        }
        __syncwarp();

        // ---- online softmax: 2 lanes per row, 32 cols each; P stored tf32 ----
        {
            int srow = lane >> 1;
            int cb = (lane & 1) * 32;
            float* sp = &Ss[(wrow + srow) * ATS + cb];
            float rmax = -1e30f;
#pragma unroll
            for (int c = 0; c < 32; c++) rmax = fmaxf(rmax, sp[c]);
            rmax = fmaxf(rmax, __shfl_xor_sync(0xffffffffu, rmax, 1));
            float mnew = fmaxf(m, rmax);
            float scale, rs = 0.f;
            if (mnew <= -1e20f) {
                scale = 1.f;
#pragma unroll
                for (int c = 0; c < 32; c++) sp[c] = 0.f;
            } else {
                scale = __expf(m - mnew);
#pragma unroll
                for (int c = 0; c < 32; c++) {
                    float p = __expf(sp[c] - mnew);
                    rs += p;
                    sp[c] = to_tf32(p);
                }
            }
            m = mnew;
            rs += __shfl_xor_sync(0xffffffffu, rs, 1);
            lsum = lsum * scale + rs;
            if ((lane & 1) == 0) scb[wrow + srow] = scale;
        }
        __syncwarp();

        // ---- rescale O, then O += P @ V (pure LDS + MMA) ----
        {
            float sc0 = scb[wrow + gid];
            float sc1 = scb[wrow + gid + 8];
#pragma unroll
            for (int ni = 0; ni < 8; ni++) {
                oacc[ni][0] *= sc0; oacc[ni][1] *= sc0;
                oacc[ni][2] *= sc1; oacc[ni][3] *= sc1;
            }
        }
#pragma unroll
        for (int ks = 0; ks < 8; ks++) {
            uint32_t pa[4];
            pa[0] = __float_as_uint(Ss[(wrow + gid) * ATS + ks * 8 + tig]);
            pa[1] = __float_as_uint(Ss[(wrow + gid + 8) * ATS + ks * 8 + tig]);
            pa[2] = __float_as_uint(Ss[(wrow + gid) * ATS + ks * 8 + tig + 4]);
            pa[3] = __float_as_uint(Ss[(wrow + gid + 8) * ATS + ks * 8 + tig + 4]);
#pragma unroll
            for (int ni = 0; ni < 8; ni++) {
                uint32_t vb[2];
                vb[0] = __float_as_uint(Vt[(ni * 8 + gid) * ATS + ks * 8 + tig]);
                vb[1] = __float_as_uint(Vt[(ni * 8 + gid) * ATS + ks * 8 + tig + 4]);
                mma_tf32(oacc[ni], pa, vb);
            }
        }
    }

    // ---- normalize and write out ----
    if ((lane & 1) == 0) lbuf[wrow + (lane >> 1)] = lsum;
    __syncwarp();
    float li0 = 1.f / lbuf[wrow + gid];
    float li1 = 1.f / lbuf[wrow + gid + 8];

#pragma unroll
    for (int ni = 0; ni < 8; ni++) {
        int col = h * HD + ni * 8 + 2 * tig;
        int row0 = b * SS + q0 + wrow + gid;
        *(float2*)(g_y + (size_t)row0 * DD + col) =
            make_float2(oacc[ni][0] * li0, oacc[ni][1] * li0);
        *(float2*)(g_y + (size_t)(row0 + 8) * DD + col) =
            make_float2(oacc[ni][2] * li1, oacc[ni][3] * li1);
    }
}

// ---------------------------------------------------------------------------
extern "C" void kernel_launch(void* const* d_in, const int* in_sizes, int n_in,
                              void* d_out, int out_size)
{
    const float* x    = (const float*)d_in[0];
    const float* ve   = (const float*)d_in[1];
    const float* cosp = (const float*)d_in[2];
    const float* sinp = (const float*)d_in[3];
    const float* Wq   = (const float*)d_in[4];
    const float* Wk   = (const float*)d_in[5];
    const float* Wv   = (const float*)d_in[6];
    const float* Wo   = (const float*)d_in[7];
    const float* Wg   = (const float*)d_in[8];
    const int*   win  = (const int*)d_in[9];
    float* out = (float*)d_out;

    float *pqkv, *py;
    cudaGetSymbolAddress((void**)&pqkv, g_qkv);
    cudaGetSymbolAddress((void**)&py, g_y);

    const int M = BB * SS;   // 4096

    // Fused QKV projection (tf32 tensor cores, pipelined)
    {
        dim3 g(QKVLD / 128, M / 128);
        gemm_tf32<1><<<g, 256>>>(x, Wq, Wk, Wv, pqkv, DD, QKVLD);
    }

    vgate_kernel<<<M, NKV * HD>>>(x, ve, Wg);
    rope_norm_kernel<<<M * (NH + NKV), HD>>>(cosp, sinp);

    // Tensor-core flash attention
    {
        int smem = (4 * 64 * ATS + 128) * sizeof(float);   // 70144 B
        cudaFuncSetAttribute(attn_tc, cudaFuncAttributeMaxDynamicSharedMemorySize, smem);
        attn_tc<<<BB * NH * (SS / 64), 128, smem>>>(win);
    }

    // Output projection (tf32 tensor cores, pipelined)
    {
        dim3 g(DD / 128, M / 128);
        gemm_tf32<0><<<g, 256>>>(py, Wo, nullptr, nullptr, out, DD, DD);
    }
}

// round 5
// speedup vs baseline: 2.6921x; 1.0216x over previous
#include <cuda_runtime.h>
#include <math.h>
#include <stdint.h>

#define BB 2
#define SS 2048
#define DD 1024
#define NH 16
#define NKV 4
#define HD 64
#define GATE_CH 12
#define EPSV 1e-6f
#define QKVLD 1536   // qkv buffer row stride: [q(1024) | k(256) | v(256)]

// Scratch (allocation-free rule: __device__ globals)
__device__ float g_qkv[BB * SS * QKVLD];   // [b*s][1536]
__device__ float g_y[BB * SS * DD];        // attention output [b*s][1024]

__device__ __forceinline__ float to_tf32(float x) {
    float r;
    asm("cvt.rna.tf32.f32 %0, %1;" : "=f"(r) : "f"(x));
    return r;
}
__device__ __forceinline__ uint32_t tf32u(float x) {
    float r;
    asm("cvt.rna.tf32.f32 %0, %1;" : "=f"(r) : "f"(x));
    return __float_as_uint(r);
}

__device__ __forceinline__ void mma_tf32(float* d, const uint32_t* a, const uint32_t* b) {
    asm volatile(
        "mma.sync.aligned.m16n8k8.row.col.f32.tf32.tf32.f32 "
        "{%0,%1,%2,%3}, {%4,%5,%6,%7}, {%8,%9}, {%0,%1,%2,%3};\n"
        : "+f"(d[0]), "+f"(d[1]), "+f"(d[2]), "+f"(d[3])
        : "r"(a[0]), "r"(a[1]), "r"(a[2]), "r"(a[3]), "r"(b[0]), "r"(b[1]));
}

__device__ __forceinline__ void cp_async16(uint32_t saddr, const void* gptr) {
    asm volatile("cp.async.cg.shared.global [%0], [%1], 16;" :: "r"(saddr), "l"(gptr));
}
#define CP_COMMIT() asm volatile("cp.async.commit_group;")
#define CP_WAIT(n)  asm volatile("cp.async.wait_group %0;" :: "n"(n))

// ---------------------------------------------------------------------------
// tf32 tensor-core GEMM, 2-stage pipelined: C[M,N] = A[M,K] @ W[K,N]
// CTA tile 128x128, BK=16, 256 threads, warp tile 64x32 (2x4 warp grid).
// ---------------------------------------------------------------------------
template<int QKV>
__global__ __launch_bounds__(256, 2) void gemm_tf32(
    const float* __restrict__ A,
    const float* __restrict__ W0, const float* __restrict__ W1,
    const float* __restrict__ W2,
    float* __restrict__ C, int K, int ldc)
{
    __shared__ float As[2][128][20];
    __shared__ float Bs[2][16][136];

    const int tid = threadIdx.x;
    const int lane = tid & 31;
    const int wid = tid >> 5;
    const int gid = lane >> 2;
    const int tig = lane & 3;
    const int warp_m = (wid >> 2) * 64;
    const int warp_n = (wid & 3) * 32;
    const int rowBase = blockIdx.y * 128;
    const int colBase = blockIdx.x * 128;

    const float* W;
    int ldw, wcol;
    if (QKV) {
        if (colBase < 1024)      { W = W0; ldw = 1024; wcol = colBase; }
        else if (colBase < 1280) { W = W1; ldw = 256;  wcol = colBase - 1024; }
        else                     { W = W2; ldw = 256;  wcol = colBase - 1280; }
    } else { W = W0; ldw = ldc; wcol = colBase; }

    const int a_r0 = tid >> 2;            const int a_c0 = (tid & 3) * 4;
    const int a_r1 = (tid + 256) >> 2;    const int a_c1 = a_c0;
    const int b_r0 = tid >> 5;            const int b_c0 = (tid & 31) * 4;
    const int b_r1 = (tid + 256) >> 5;    const int b_c1 = b_c0;

    const float* Abase0 = A + (size_t)(rowBase + a_r0) * K + a_c0;
    const float* Abase1 = A + (size_t)(rowBase + a_r1) * K + a_c1;
    const float* Wbase0 = W + (size_t)b_r0 * ldw + wcol + b_c0;
    const float* Wbase1 = W + (size_t)b_r1 * ldw + wcol + b_c1;

    float acc[4][4][4] = {};
    float4 ra0, ra1, rb0, rb1;

    ra0 = *(const float4*)Abase0;
    ra1 = *(const float4*)Abase1;
    rb0 = *(const float4*)Wbase0;
    rb1 = *(const float4*)Wbase1;
    {
        float4 t;
        t = ra0; t.x=to_tf32(t.x); t.y=to_tf32(t.y); t.z=to_tf32(t.z); t.w=to_tf32(t.w);
        *(float4*)&As[0][a_r0][a_c0] = t;
        t = ra1; t.x=to_tf32(t.x); t.y=to_tf32(t.y); t.z=to_tf32(t.z); t.w=to_tf32(t.w);
        *(float4*)&As[0][a_r1][a_c1] = t;
        t = rb0; t.x=to_tf32(t.x); t.y=to_tf32(t.y); t.z=to_tf32(t.z); t.w=to_tf32(t.w);
        *(float4*)&Bs[0][b_r0][b_c0] = t;
        t = rb1; t.x=to_tf32(t.x); t.y=to_tf32(t.y); t.z=to_tf32(t.z); t.w=to_tf32(t.w);
        *(float4*)&Bs[0][b_r1][b_c1] = t;
    }
    __syncthreads();

    const int iters = K / 16;
    for (int it = 0; it < iters; it++) {
        const int s = it & 1;
        const bool more = (it + 1) < iters;
        if (more) {
            int k0n = (it + 1) * 16;
            ra0 = *(const float4*)(Abase0 + k0n);
            ra1 = *(const float4*)(Abase1 + k0n);
            rb0 = *(const float4*)(Wbase0 + (size_t)k0n * ldw);
            rb1 = *(const float4*)(Wbase1 + (size_t)k0n * ldw);
        }

#pragma unroll
        for (int ks = 0; ks < 16; ks += 8) {
            uint32_t af[4][4], bf[4][2];
#pragma unroll
            for (int mi = 0; mi < 4; mi++) {
                int r0 = warp_m + mi * 16 + gid;
                af[mi][0] = __float_as_uint(As[s][r0][ks + tig]);
                af[mi][1] = __float_as_uint(As[s][r0 + 8][ks + tig]);
                af[mi][2] = __float_as_uint(As[s][r0][ks + tig + 4]);
                af[mi][3] = __float_as_uint(As[s][r0 + 8][ks + tig + 4]);
            }
#pragma unroll
            for (int ni = 0; ni < 4; ni++) {
                int c0 = warp_n + ni * 8 + gid;
                bf[ni][0] = __float_as_uint(Bs[s][ks + tig][c0]);
                bf[ni][1] = __float_as_uint(Bs[s][ks + tig + 4][c0]);
            }
#pragma unroll
            for (int mi = 0; mi < 4; mi++)
#pragma unroll
                for (int ni = 0; ni < 4; ni++)
                    mma_tf32(acc[mi][ni], af[mi], bf[ni]);
        }

        if (more) {
            const int d = s ^ 1;
            float4 t;
            t = ra0; t.x=to_tf32(t.x); t.y=to_tf32(t.y); t.z=to_tf32(t.z); t.w=to_tf32(t.w);
            *(float4*)&As[d][a_r0][a_c0] = t;
            t = ra1; t.x=to_tf32(t.x); t.y=to_tf32(t.y); t.z=to_tf32(t.z); t.w=to_tf32(t.w);
            *(float4*)&As[d][a_r1][a_c1] = t;
            t = rb0; t.x=to_tf32(t.x); t.y=to_tf32(t.y); t.z=to_tf32(t.z); t.w=to_tf32(t.w);
            *(float4*)&Bs[d][b_r0][b_c0] = t;
            t = rb1; t.x=to_tf32(t.x); t.y=to_tf32(t.y); t.z=to_tf32(t.z); t.w=to_tf32(t.w);
            *(float4*)&Bs[d][b_r1][b_c1] = t;
        }
        __syncthreads();
    }

#pragma unroll
    for (int mi = 0; mi < 4; mi++) {
#pragma unroll
        for (int ni = 0; ni < 4; ni++) {
            int row = rowBase + warp_m + mi * 16 + gid;
            int col = colBase + warp_n + ni * 8 + 2 * tig;
            *(float2*)(C + (size_t)row * ldc + col) =
                make_float2(acc[mi][ni][0], acc[mi][ni][1]);
            *(float2*)(C + (size_t)(row + 8) * ldc + col) =
                make_float2(acc[mi][ni][2], acc[mi][ni][3]);
        }
    }
}

// ---------------------------------------------------------------------------
// V gate epilogue
// ---------------------------------------------------------------------------
__global__ void vgate_kernel(const float* __restrict__ x,
                             const float* __restrict__ ve,
                             const float* __restrict__ Wg)
{
    int bs = blockIdx.x;
    int t = threadIdx.x;
    int kvh = t >> 6;
    const float* xr = x + (size_t)bs * DD;
    float g = 0.f;
#pragma unroll
    for (int c = 0; c < GATE_CH; c++) g += xr[c] * Wg[c * NKV + kvh];
    g = 3.f / (1.f + __expf(-g));
    g_qkv[(size_t)bs * QKVLD + 1280 + t] += g * ve[(size_t)bs * (NKV * HD) + t];
}

// ---------------------------------------------------------------------------
// RoPE + RMSNorm (*1.2) for q and k in place (in qkv buffer).
// ---------------------------------------------------------------------------
__global__ void rope_norm_kernel(const float* __restrict__ cosp,
                                 const float* __restrict__ sinp)
{
    int blk = blockIdx.x;
    int hh = blk % (NH + NKV);
    int bs = blk / (NH + NKV);
    int s = bs % SS;

    float* ptr = g_qkv + (size_t)bs * QKVLD +
                 ((hh < NH) ? hh * HD : 1024 + (hh - NH) * HD);

    int d = threadIdx.x;
    int half = d & 31;
    float c  = cosp[s * 32 + half];
    float sn = sinp[s * 32 + half];
    float x1 = ptr[half];
    float x2 = ptr[half + 32];
    float rot = (d < 32) ? (x1 * c + x2 * sn) : (-x1 * sn + x2 * c);

    __shared__ float red[2];
    float v = rot * rot;
#pragma unroll
    for (int o = 16; o > 0; o >>= 1) v += __shfl_xor_sync(0xffffffffu, v, o);
    if ((d & 31) == 0) red[d >> 5] = v;
    __syncthreads();
    float total = red[0] + red[1];
    float r = rsqrtf(total * (1.f / HD) + EPSV) * 1.2f;
    ptr[d] = rot * r;
}

// ---------------------------------------------------------------------------
// Tensor-core flash attention (tf32, hi/lo-compensated QK^T).
// grid = B*NH*(S/64), block = 128 (4 warps; warp w owns query rows 16w..16w+15).
// K/V double-buffered via cp.async: Kb[2][64][68] | Vb[2][64][68] | Ss[64][68]
// fp32 in smem; hi/lo tf32 split done inline at fragment load (R3 dataflow).
// ---------------------------------------------------------------------------
#define ATS 68   // smem row stride
#define TILEF (64 * ATS)
__global__ __launch_bounds__(128) void attn_tc(const int* __restrict__ winp)
{
    const int win = *winp;
    int bid = blockIdx.x;
    int qt = bid & 31;
    int bh = bid >> 5;
    int h = bh % NH;
    int b = bh / NH;
    int q0 = qt * 64;
    int kvh = h / (NH / NKV);

    const int tid = threadIdx.x;
    const int lane = tid & 31;
    const int warp = tid >> 5;
    const int wrow = warp * 16;
    const int gid = lane >> 2;
    const int tig = lane & 3;

    extern __shared__ float sm[];
    float* Ss   = sm + 4 * TILEF;
    float* scb  = sm + 5 * TILEF;
    float* lbuf = scb + 64;
    uint32_t smbase = (uint32_t)__cvta_generic_to_shared(sm);

    // staging coordinates: each thread handles 8 (row, c4) pairs per buffer
    const int st_r  = tid >> 4;          // 0..7  (+8 per step)
    const int st_c4 = (tid & 15) * 4;    // 0..60
    const float* kvsrc = g_qkv + (size_t)(b * SS + st_r) * QKVLD + 1024 + kvh * HD + st_c4;

    // ---- stage Q tile into Ss, pull hi/lo fragments into registers ----
    for (int i = tid; i < 64 * 16; i += 128) {
        int r = i >> 4;
        int c4 = (i & 15) * 4;
        *(float4*)&Ss[r * ATS + c4] =
            *(const float4*)(g_qkv + (size_t)(b * SS + q0 + r) * QKVLD + h * HD + c4);
    }
    __syncthreads();

    uint32_t ahi[8][4], alo[8][4];
#pragma unroll
    for (int ks = 0; ks < 8; ks++) {
#pragma unroll
        for (int idx = 0; idx < 4; idx++) {
            int row = wrow + gid + ((idx & 1) << 3);
            int col = ks * 8 + tig + ((idx >> 1) << 2);
            float v = Ss[row * ATS + col] * 0.125f;
            float hi = to_tf32(v);
            ahi[ks][idx] = __float_as_uint(hi);
            alo[ks][idx] = tf32u(v - hi);
        }
    }

    float m = -1e30f, lsum = 0.f;
    float oacc[8][4] = {};

    int kmin = q0 - win + 1;
    if (kmin < 0) kmin = 0;
    int t0 = kmin >> 6;
    int t1 = (q0 + 63) >> 6;

    // ---- prologue: async-stage tile t0 into buffer 0 ----
    {
        const float* src = kvsrc + (size_t)(t0 << 6) * QKVLD;
        uint32_t kdst = smbase + (0 * TILEF + st_r * ATS + st_c4) * 4;
        uint32_t vdst = smbase + (2 * TILEF + st_r * ATS + st_c4) * 4;
#pragma unroll
        for (int j = 0; j < 8; j++) {
            cp_async16(kdst + j * 8 * ATS * 4, src + (size_t)j * 8 * QKVLD);
            cp_async16(vdst + j * 8 * ATS * 4, src + (size_t)j * 8 * QKVLD + 256);
        }
        CP_COMMIT();
    }

    for (int t = t0; t <= t1; t++) {
        int kb = t << 6;
        const int buf = (t - t0) & 1;
        __syncthreads();   // everyone done reading buf^1 from iter t-1
        if (t < t1) {
            const float* src = kvsrc + (size_t)((t + 1) << 6) * QKVLD;
            uint32_t kdst = smbase + ((buf ^ 1) * TILEF + st_r * ATS + st_c4) * 4;
            uint32_t vdst = smbase + ((2 + (buf ^ 1)) * TILEF + st_r * ATS + st_c4) * 4;
#pragma unroll
            for (int j = 0; j < 8; j++) {
                cp_async16(kdst + j * 8 * ATS * 4, src + (size_t)j * 8 * QKVLD);
                cp_async16(vdst + j * 8 * ATS * 4, src + (size_t)j * 8 * QKVLD + 256);
            }
            CP_COMMIT();
            CP_WAIT(1);
        } else {
            CP_WAIT(0);
        }
        __syncthreads();   // staged data visible to all

        const float* Ks = sm + buf * TILEF;
        const float* Vs = sm + (2 + buf) * TILEF;

        // ---- S = Q @ K^T (hi/lo compensated, inline K split) ----
        float accS[8][4] = {};
#pragma unroll
        for (int ks = 0; ks < 8; ks++) {
#pragma unroll
            for (int ni = 0; ni < 8; ni++) {
                const float* kr = &Ks[(ni * 8 + gid) * ATS + ks * 8 + tig];
                float k0 = kr[0], k1 = kr[4];
                float h0 = to_tf32(k0), h1 = to_tf32(k1);
                uint32_t bhi[2] = { __float_as_uint(h0), __float_as_uint(h1) };
                uint32_t blo[2] = { tf32u(k0 - h0), tf32u(k1 - h1) };
                mma_tf32(accS[ni], ahi[ks], bhi);
                mma_tf32(accS[ni], alo[ks], bhi);
                mma_tf32(accS[ni], ahi[ks], blo);
            }
        }

        // ---- write masked S to smem (warp-private rows) ----
#pragma unroll
        for (int ni = 0; ni < 8; ni++) {
#pragma unroll
            for (int j = 0; j < 4; j++) {
                int col = ni * 8 + 2 * tig + (j & 1);
                int r = gid + ((j >> 1) << 3);
                int qpos = q0 + wrow + r;
                int kpos = kb + col;
                bool ok = (kpos <= qpos) && (kpos >= qpos - win + 1);
                Ss[(wrow + r) * ATS + col] = ok ? accS[ni][j] : -1e30f;
            }
        }
        __syncwarp();

        // ---- online softmax: 2 lanes per row, 32 cols each ----
        {
            int srow = lane >> 1;
            int cb = (lane & 1) * 32;
            float* sp = &Ss[(wrow + srow) * ATS + cb];
            float rmax = -1e30f;
#pragma unroll
            for (int c = 0; c < 32; c++) rmax = fmaxf(rmax, sp[c]);
            rmax = fmaxf(rmax, __shfl_xor_sync(0xffffffffu, rmax, 1));
            float mnew = fmaxf(m, rmax);
            float scale, rs = 0.f;
            if (mnew <= -1e20f) {
                scale = 1.f;
#pragma unroll
                for (int c = 0; c < 32; c++) sp[c] = 0.f;
            } else {
                scale = __expf(m - mnew);
#pragma unroll
                for (int c = 0; c < 32; c++) {
                    float p = __expf(sp[c] - mnew);
                    rs += p;
                    sp[c] = to_tf32(p);
                }
            }
            m = mnew;
            rs += __shfl_xor_sync(0xffffffffu, rs, 1);
            lsum = lsum * scale + rs;
            if ((lane & 1) == 0) scb[wrow + srow] = scale;
        }
        __syncwarp();

        // ---- rescale O, then O += P @ V ----
        {
            float sc0 = scb[wrow + gid];
            float sc1 = scb[wrow + gid + 8];
#pragma unroll
            for (int ni = 0; ni < 8; ni++) {
                oacc[ni][0] *= sc0; oacc[ni][1] *= sc0;
                oacc[ni][2] *= sc1; oacc[ni][3] *= sc1;
            }
        }
#pragma unroll
        for (int ks = 0; ks < 8; ks++) {
            uint32_t pa[4];
            pa[0] = __float_as_uint(Ss[(wrow + gid) * ATS + ks * 8 + tig]);
            pa[1] = __float_as_uint(Ss[(wrow + gid + 8) * ATS + ks * 8 + tig]);
            pa[2] = __float_as_uint(Ss[(wrow + gid) * ATS + ks * 8 + tig + 4]);
            pa[3] = __float_as_uint(Ss[(wrow + gid + 8) * ATS + ks * 8 + tig + 4]);
#pragma unroll
            for (int ni = 0; ni < 8; ni++) {
                uint32_t vb[2];
                vb[0] = tf32u(Vs[(ks * 8 + tig) * ATS + ni * 8 + gid]);
                vb[1] = tf32u(Vs[(ks * 8 + tig + 4) * ATS + ni * 8 + gid]);
                mma_tf32(oacc[ni], pa, vb);
            }
        }
    }

    // ---- normalize and write out ----
    if ((lane & 1) == 0) lbuf[wrow + (lane >> 1)] = lsum;
    __syncwarp();
    float li0 = 1.f / lbuf[wrow + gid];
    float li1 = 1.f / lbuf[wrow + gid + 8];

#pragma unroll
    for (int ni = 0; ni < 8; ni++) {
        int col = h * HD + ni * 8 + 2 * tig;
        int row0 = b * SS + q0 + wrow + gid;
        *(float2*)(g_y + (size_t)row0 * DD + col) =
            make_float2(oacc[ni][0] * li0, oacc[ni][1] * li0);
        *(float2*)(g_y + (size_t)(row0 + 8) * DD + col) =
            make_float2(oacc[ni][2] * li1, oacc[ni][3] * li1);
    }
}

// ---------------------------------------------------------------------------
extern "C" void kernel_launch(void* const* d_in, const int* in_sizes, int n_in,
                              void* d_out, int out_size)
{
    const float* x    = (const float*)d_in[0];
    const float* ve   = (const float*)d_in[1];
    const float* cosp = (const float*)d_in[2];
    const float* sinp = (const float*)d_in[3];
    const float* Wq   = (const float*)d_in[4];
    const float* Wk   = (const float*)d_in[5];
    const float* Wv   = (const float*)d_in[6];
    const float* Wo   = (const float*)d_in[7];
    const float* Wg   = (const float*)d_in[8];
    const int*   win  = (const int*)d_in[9];
    float* out = (float*)d_out;

    float *pqkv, *py;
    cudaGetSymbolAddress((void**)&pqkv, g_qkv);
    cudaGetSymbolAddress((void**)&py, g_y);

    const int M = BB * SS;   // 4096

    // Fused QKV projection (tf32 tensor cores, pipelined)
    {
        dim3 g(QKVLD / 128, M / 128);
        gemm_tf32<1><<<g, 256>>>(x, Wq, Wk, Wv, pqkv, DD, QKVLD);
    }

    vgate_kernel<<<M, NKV * HD>>>(x, ve, Wg);
    rope_norm_kernel<<<M * (NH + NKV), HD>>>(cosp, sinp);

    // Tensor-core flash attention (cp.async double-buffered K/V)
    {
        int smem = (5 * TILEF + 128) * sizeof(float);   // 87552 B
        cudaFuncSetAttribute(attn_tc, cudaFuncAttributeMaxDynamicSharedMemorySize, smem);
        attn_tc<<<BB * NH * (SS / 64), 128, smem>>>(win);
    }

    // Output projection (tf32 tensor cores, pipelined)
    {
        dim3 g(DD / 128, M / 128);
        gemm_tf32<0><<<g, 256>>>(py, Wo, nullptr, nullptr, out, DD, DD);
    }
}

// round 6
// speedup vs baseline: 3.0095x; 1.1179x over previous
#include <cuda_runtime.h>
#include <cuda_bf16.h>
#include <math.h>
#include <stdint.h>

#define BB 2
#define SS 2048
#define DD 1024
#define NH 16
#define NKV 4
#define HD 64
#define GATE_CH 12
#define EPSV 1e-6f
#define QKVLD 1536   // qkv buffer row stride: [q(1024) | k(256) | v(256)]

// Scratch (allocation-free rule: __device__ globals)
__device__ float g_qkv[BB * SS * QKVLD];     // [b*s][1536]
__device__ float g_y[BB * SS * DD];          // attention output [b*s][1024]
// packed bf16 hi/lo (u32 = odd<<16 | even), 64 u32 per head-vector:
// [0..31] = hi pairs, [32..63] = lo pairs
__device__ uint32_t g_qpk[BB * SS * NH * 64];
__device__ uint32_t g_kpk[BB * SS * NKV * 64];

__device__ __forceinline__ float to_tf32(float x) {
    float r;
    asm("cvt.rna.tf32.f32 %0, %1;" : "=f"(r) : "f"(x));
    return r;
}
__device__ __forceinline__ uint32_t pack_bf16(float e /*lower k*/, float o /*upper k*/) {
    uint16_t a = __bfloat16_as_ushort(__float2bfloat16(e));
    uint16_t b = __bfloat16_as_ushort(__float2bfloat16(o));
    return ((uint32_t)b << 16) | a;
}

__device__ __forceinline__ void mma_tf32(float* d, const uint32_t* a, const uint32_t* b) {
    asm volatile(
        "mma.sync.aligned.m16n8k8.row.col.f32.tf32.tf32.f32 "
        "{%0,%1,%2,%3}, {%4,%5,%6,%7}, {%8,%9}, {%0,%1,%2,%3};\n"
        : "+f"(d[0]), "+f"(d[1]), "+f"(d[2]), "+f"(d[3])
        : "r"(a[0]), "r"(a[1]), "r"(a[2]), "r"(a[3]), "r"(b[0]), "r"(b[1]));
}
__device__ __forceinline__ void mma_bf16(float* d, const uint32_t* a, const uint32_t* b) {
    asm volatile(
        "mma.sync.aligned.m16n8k16.row.col.f32.bf16.bf16.f32 "
        "{%0,%1,%2,%3}, {%4,%5,%6,%7}, {%8,%9}, {%0,%1,%2,%3};\n"
        : "+f"(d[0]), "+f"(d[1]), "+f"(d[2]), "+f"(d[3])
        : "r"(a[0]), "r"(a[1]), "r"(a[2]), "r"(a[3]), "r"(b[0]), "r"(b[1]));
}

__device__ __forceinline__ void cp_async16(uint32_t saddr, const void* gptr) {
    asm volatile("cp.async.cg.shared.global [%0], [%1], 16;" :: "r"(saddr), "l"(gptr));
}
#define CP_COMMIT() asm volatile("cp.async.commit_group;")
#define CP_WAIT(n)  asm volatile("cp.async.wait_group %0;" :: "n"(n))

// ---------------------------------------------------------------------------
// tf32 tensor-core GEMM, 2-stage pipelined (unchanged from R4/R5)
// ---------------------------------------------------------------------------
template<int QKV>
__global__ __launch_bounds__(256, 2) void gemm_tf32(
    const float* __restrict__ A,
    const float* __restrict__ W0, const float* __restrict__ W1,
    const float* __restrict__ W2,
    float* __restrict__ C, int K, int ldc)
{
    __shared__ float As[2][128][20];
    __shared__ float Bs[2][16][136];

    const int tid = threadIdx.x;
    const int lane = tid & 31;
    const int wid = tid >> 5;
    const int gid = lane >> 2;
    const int tig = lane & 3;
    const int warp_m = (wid >> 2) * 64;
    const int warp_n = (wid & 3) * 32;
    const int rowBase = blockIdx.y * 128;
    const int colBase = blockIdx.x * 128;

    const float* W;
    int ldw, wcol;
    if (QKV) {
        if (colBase < 1024)      { W = W0; ldw = 1024; wcol = colBase; }
        else if (colBase < 1280) { W = W1; ldw = 256;  wcol = colBase - 1024; }
        else                     { W = W2; ldw = 256;  wcol = colBase - 1280; }
    } else { W = W0; ldw = ldc; wcol = colBase; }

    const int a_r0 = tid >> 2;            const int a_c0 = (tid & 3) * 4;
    const int a_r1 = (tid + 256) >> 2;    const int a_c1 = a_c0;
    const int b_r0 = tid >> 5;            const int b_c0 = (tid & 31) * 4;
    const int b_r1 = (tid + 256) >> 5;    const int b_c1 = b_c0;

    const float* Abase0 = A + (size_t)(rowBase + a_r0) * K + a_c0;
    const float* Abase1 = A + (size_t)(rowBase + a_r1) * K + a_c1;
    const float* Wbase0 = W + (size_t)b_r0 * ldw + wcol + b_c0;
    const float* Wbase1 = W + (size_t)b_r1 * ldw + wcol + b_c1;

    float acc[4][4][4] = {};
    float4 ra0, ra1, rb0, rb1;

    ra0 = *(const float4*)Abase0;
    ra1 = *(const float4*)Abase1;
    rb0 = *(const float4*)Wbase0;
    rb1 = *(const float4*)Wbase1;
    {
        float4 t;
        t = ra0; t.x=to_tf32(t.x); t.y=to_tf32(t.y); t.z=to_tf32(t.z); t.w=to_tf32(t.w);
        *(float4*)&As[0][a_r0][a_c0] = t;
        t = ra1; t.x=to_tf32(t.x); t.y=to_tf32(t.y); t.z=to_tf32(t.z); t.w=to_tf32(t.w);
        *(float4*)&As[0][a_r1][a_c1] = t;
        t = rb0; t.x=to_tf32(t.x); t.y=to_tf32(t.y); t.z=to_tf32(t.z); t.w=to_tf32(t.w);
        *(float4*)&Bs[0][b_r0][b_c0] = t;
        t = rb1; t.x=to_tf32(t.x); t.y=to_tf32(t.y); t.z=to_tf32(t.z); t.w=to_tf32(t.w);
        *(float4*)&Bs[0][b_r1][b_c1] = t;
    }
    __syncthreads();

    const int iters = K / 16;
    for (int it = 0; it < iters; it++) {
        const int s = it & 1;
        const bool more = (it + 1) < iters;
        if (more) {
            int k0n = (it + 1) * 16;
            ra0 = *(const float4*)(Abase0 + k0n);
            ra1 = *(const float4*)(Abase1 + k0n);
            rb0 = *(const float4*)(Wbase0 + (size_t)k0n * ldw);
            rb1 = *(const float4*)(Wbase1 + (size_t)k0n * ldw);
        }

#pragma unroll
        for (int ks = 0; ks < 16; ks += 8) {
            uint32_t af[4][4], bf[4][2];
#pragma unroll
            for (int mi = 0; mi < 4; mi++) {
                int r0 = warp_m + mi * 16 + gid;
                af[mi][0] = __float_as_uint(As[s][r0][ks + tig]);
                af[mi][1] = __float_as_uint(As[s][r0 + 8][ks + tig]);
                af[mi][2] = __float_as_uint(As[s][r0][ks + tig + 4]);
                af[mi][3] = __float_as_uint(As[s][r0 + 8][ks + tig + 4]);
            }
#pragma unroll
            for (int ni = 0; ni < 4; ni++) {
                int c0 = warp_n + ni * 8 + gid;
                bf[ni][0] = __float_as_uint(Bs[s][ks + tig][c0]);
                bf[ni][1] = __float_as_uint(Bs[s][ks + tig + 4][c0]);
            }
#pragma unroll
            for (int mi = 0; mi < 4; mi++)
#pragma unroll
                for (int ni = 0; ni < 4; ni++)
                    mma_tf32(acc[mi][ni], af[mi], bf[ni]);
        }

        if (more) {
            const int d = s ^ 1;
            float4 t;
            t = ra0; t.x=to_tf32(t.x); t.y=to_tf32(t.y); t.z=to_tf32(t.z); t.w=to_tf32(t.w);
            *(float4*)&As[d][a_r0][a_c0] = t;
            t = ra1; t.x=to_tf32(t.x); t.y=to_tf32(t.y); t.z=to_tf32(t.z); t.w=to_tf32(t.w);
            *(float4*)&As[d][a_r1][a_c1] = t;
            t = rb0; t.x=to_tf32(t.x); t.y=to_tf32(t.y); t.z=to_tf32(t.z); t.w=to_tf32(t.w);
            *(float4*)&Bs[d][b_r0][b_c0] = t;
            t = rb1; t.x=to_tf32(t.x); t.y=to_tf32(t.y); t.z=to_tf32(t.z); t.w=to_tf32(t.w);
            *(float4*)&Bs[d][b_r1][b_c1] = t;
        }
        __syncthreads();
    }

#pragma unroll
    for (int mi = 0; mi < 4; mi++) {
#pragma unroll
        for (int ni = 0; ni < 4; ni++) {
            int row = rowBase + warp_m + mi * 16 + gid;
            int col = colBase + warp_n + ni * 8 + 2 * tig;
            *(float2*)(C + (size_t)row * ldc + col) =
                make_float2(acc[mi][ni][0], acc[mi][ni][1]);
            *(float2*)(C + (size_t)(row + 8) * ldc + col) =
                make_float2(acc[mi][ni][2], acc[mi][ni][3]);
        }
    }
}

// ---------------------------------------------------------------------------
// V gate epilogue; result rounded to tf32 in place (PV consumes tf32 anyway)
// ---------------------------------------------------------------------------
__global__ void vgate_kernel(const float* __restrict__ x,
                             const float* __restrict__ ve,
                             const float* __restrict__ Wg)
{
    int bs = blockIdx.x;
    int t = threadIdx.x;
    int kvh = t >> 6;
    const float* xr = x + (size_t)bs * DD;
    float g = 0.f;
#pragma unroll
    for (int c = 0; c < GATE_CH; c++) g += xr[c] * Wg[c * NKV + kvh];
    g = 3.f / (1.f + __expf(-g));
    float* vp = &g_qkv[(size_t)bs * QKVLD + 1280 + t];
    *vp = to_tf32(*vp + g * ve[(size_t)bs * (NKV * HD) + t]);
}

// ---------------------------------------------------------------------------
// RoPE + RMSNorm (*1.2), emits packed bf16 hi/lo q (scale 1.2*0.125 folded) & k.
// grid = B*S*(NH+NKV), block = 64
// ---------------------------------------------------------------------------
__global__ void rope_norm_kernel(const float* __restrict__ cosp,
                                 const float* __restrict__ sinp)
{
    int blk = blockIdx.x;
    int hh = blk % (NH + NKV);
    int bs = blk / (NH + NKV);
    int s = bs % SS;

    const float* ptr = g_qkv + (size_t)bs * QKVLD +
                       ((hh < NH) ? hh * HD : 1024 + (hh - NH) * HD);

    int d = threadIdx.x;
    int half = d & 31;
    float c  = cosp[s * 32 + half];
    float sn = sinp[s * 32 + half];
    float x1 = ptr[half];
    float x2 = ptr[half + 32];
    float rot = (d < 32) ? (x1 * c + x2 * sn) : (-x1 * sn + x2 * c);

    __shared__ float red[2];
    float v = rot * rot;
#pragma unroll
    for (int o = 16; o > 0; o >>= 1) v += __shfl_xor_sync(0xffffffffu, v, o);
    if ((d & 31) == 0) red[d >> 5] = v;
    __syncthreads();
    float total = red[0] + red[1];
    float r = rsqrtf(total * (1.f / HD) + EPSV) * 1.2f;
    float val = rot * r;
    if (hh < NH) val *= 0.125f;   // fold 1/sqrt(hd) into q

    // split into bf16 hi + bf16 lo, pack pairs (even d = low half)
    float hif = __bfloat162float(__float2bfloat16(val));
    float lof = val - hif;
    float val_o = __shfl_down_sync(0xffffffffu, val, 1);
    float lof_o = __shfl_down_sync(0xffffffffu, lof, 1);

    if ((d & 1) == 0) {
        uint32_t hp = pack_bf16(val, val_o);
        uint32_t lp = pack_bf16(lof, lof_o);
        uint32_t* out = (hh < NH)
            ? &g_qpk[((size_t)bs * NH + hh) * 64]
            : &g_kpk[((size_t)bs * NKV + (hh - NH)) * 64];
        out[d >> 1]        = hp;
        out[32 + (d >> 1)] = lp;
    }
}

// ---------------------------------------------------------------------------
// Tensor-core flash attention.
// QK^T: bf16 m16n8k16, hi/lo compensated (3 MMAs), splits precomputed.
// PV:   tf32 m16n8k8 (V pre-rounded by vgate).
// grid = B*NH*(S/64), block = 128. K(packed)/V double-buffered via cp.async.
// smem u32/f32 units: Khl[2][64][68] | Vb[2][64][68] | Ss[64][68] | scb | lbuf
// ---------------------------------------------------------------------------
#define ATS 68
#define TILEF (64 * ATS)
__global__ __launch_bounds__(128) void attn_tc(const int* __restrict__ winp)
{
    const int win = *winp;
    int bid = blockIdx.x;
    int qt = bid & 31;
    int bh = bid >> 5;
    int h = bh % NH;
    int b = bh / NH;
    int q0 = qt * 64;
    int kvh = h / (NH / NKV);

    const int tid = threadIdx.x;
    const int lane = tid & 31;
    const int warp = tid >> 5;
    const int wrow = warp * 16;
    const int gid = lane >> 2;
    const int tig = lane & 3;

    extern __shared__ float sm[];
    uint32_t* Khl0 = (uint32_t*)sm;                 // 2 buffers of packed K
    float* Ss   = sm + 4 * TILEF;
    float* scb  = sm + 5 * TILEF;
    float* lbuf = scb + 64;
    uint32_t smbase = (uint32_t)__cvta_generic_to_shared(sm);

    // staging coords: 128 threads cover 64 rows x 64 u32 in 8 steps of 16B
    const int st_r  = tid >> 4;          // 0..7 (+8 per step)
    const int st_c4 = (tid & 15) * 4;    // 0..60

    // ---- stage packed Q tile into Ss (as u32), build A fragments ----
    {
        uint32_t* Qs = (uint32_t*)Ss;
        for (int i = tid; i < 64 * 16; i += 128) {
            int r = i >> 4;
            int c4 = (i & 15) * 4;
            *(uint4*)&Qs[r * ATS + c4] =
                *(const uint4*)(g_qpk + ((size_t)(b * SS + q0 + r) * NH + h) * 64 + c4);
        }
    }
    __syncthreads();

    uint32_t ahi[4][4], alo[4][4];
    {
        const uint32_t* Qs = (const uint32_t*)Ss;
#pragma unroll
        for (int ks = 0; ks < 4; ks++) {
            int cb = ks * 8 + tig;
            ahi[ks][0] = Qs[(wrow + gid) * ATS + cb];
            ahi[ks][1] = Qs[(wrow + gid + 8) * ATS + cb];
            ahi[ks][2] = Qs[(wrow + gid) * ATS + cb + 4];
            ahi[ks][3] = Qs[(wrow + gid + 8) * ATS + cb + 4];
            alo[ks][0] = Qs[(wrow + gid) * ATS + 32 + cb];
            alo[ks][1] = Qs[(wrow + gid + 8) * ATS + 32 + cb];
            alo[ks][2] = Qs[(wrow + gid) * ATS + 32 + cb + 4];
            alo[ks][3] = Qs[(wrow + gid + 8) * ATS + 32 + cb + 4];
        }
    }

    float m = -1e30f, lsum = 0.f;
    float oacc[8][4] = {};

    int kmin = q0 - win + 1;
    if (kmin < 0) kmin = 0;
    int t0 = kmin >> 6;
    int t1 = (q0 + 63) >> 6;

    // ---- prologue: async-stage tile t0 into buffer 0 ----
    {
        int kb = t0 << 6;
        const uint32_t* ksrc = g_kpk + ((size_t)(b * SS + kb + st_r) * NKV + kvh) * 64 + st_c4;
        const float* vsrc = g_qkv + (size_t)(b * SS + kb + st_r) * QKVLD + 1280 + kvh * HD + st_c4;
        uint32_t kdst = smbase + (0 * TILEF + st_r * ATS + st_c4) * 4;
        uint32_t vdst = smbase + (2 * TILEF + st_r * ATS + st_c4) * 4;
#pragma unroll
        for (int j = 0; j < 8; j++) {
            cp_async16(kdst + j * 8 * ATS * 4, ksrc + (size_t)j * 8 * NKV * 64);
            cp_async16(vdst + j * 8 * ATS * 4, vsrc + (size_t)j * 8 * QKVLD);
        }
        CP_COMMIT();
    }

    for (int t = t0; t <= t1; t++) {
        int kb = t << 6;
        const int buf = (t - t0) & 1;
        __syncthreads();   // everyone done reading buf^1 from iter t-1
        if (t < t1) {
            int nb = (t + 1) << 6;
            const uint32_t* ksrc = g_kpk + ((size_t)(b * SS + nb + st_r) * NKV + kvh) * 64 + st_c4;
            const float* vsrc = g_qkv + (size_t)(b * SS + nb + st_r) * QKVLD + 1280 + kvh * HD + st_c4;
            uint32_t kdst = smbase + ((buf ^ 1) * TILEF + st_r * ATS + st_c4) * 4;
            uint32_t vdst = smbase + ((2 + (buf ^ 1)) * TILEF + st_r * ATS + st_c4) * 4;
#pragma unroll
            for (int j = 0; j < 8; j++) {
                cp_async16(kdst + j * 8 * ATS * 4, ksrc + (size_t)j * 8 * NKV * 64);
                cp_async16(vdst + j * 8 * ATS * 4, vsrc + (size_t)j * 8 * QKVLD);
            }
            CP_COMMIT();
            CP_WAIT(1);
        } else {
            CP_WAIT(0);
        }
        __syncthreads();

        const uint32_t* Khl = Khl0 + buf * TILEF;
        const float* Vs = sm + (2 + buf) * TILEF;

        // ---- S = Q @ K^T : bf16 hi/lo, pure LDS + MMA ----
        float accS[8][4] = {};
#pragma unroll
        for (int ks = 0; ks < 4; ks++) {
#pragma unroll
            for (int ni = 0; ni < 8; ni++) {
                const uint32_t* kr = &Khl[(ni * 8 + gid) * ATS + ks * 8 + tig];
                uint32_t bh2[2] = { kr[0],  kr[4] };
                uint32_t bl2[2] = { kr[32], kr[36] };
                mma_bf16(accS[ni], ahi[ks], bh2);
                mma_bf16(accS[ni], alo[ks], bh2);
                mma_bf16(accS[ni], ahi[ks], bl2);
            }
        }

        // ---- write masked S to smem (warp-private rows) ----
#pragma unroll
        for (int ni = 0; ni < 8; ni++) {
#pragma unroll
            for (int j = 0; j < 4; j++) {
                int col = ni * 8 + 2 * tig + (j & 1);
                int r = gid + ((j >> 1) << 3);
                int qpos = q0 + wrow + r;
                int kpos = kb + col;
                bool ok = (kpos <= qpos) && (kpos >= qpos - win + 1);
                Ss[(wrow + r) * ATS + col] = ok ? accS[ni][j] : -1e30f;
            }
        }
        __syncwarp();

        // ---- online softmax: 2 lanes per row, 32 cols each ----
        {
            int srow = lane >> 1;
            int cb = (lane & 1) * 32;
            float* sp = &Ss[(wrow + srow) * ATS + cb];
            float rmax = -1e30f;
#pragma unroll
            for (int c = 0; c < 32; c++) rmax = fmaxf(rmax, sp[c]);
            rmax = fmaxf(rmax, __shfl_xor_sync(0xffffffffu, rmax, 1));
            float mnew = fmaxf(m, rmax);
            float scale, rs = 0.f;
            if (mnew <= -1e20f) {
                scale = 1.f;
#pragma unroll
                for (int c = 0; c < 32; c++) sp[c] = 0.f;
            } else {
                scale = __expf(m - mnew);
#pragma unroll
                for (int c = 0; c < 32; c++) {
                    float p = __expf(sp[c] - mnew);
                    rs += p;
                    sp[c] = to_tf32(p);
                }
            }
            m = mnew;
            rs += __shfl_xor_sync(0xffffffffu, rs, 1);
            lsum = lsum * scale + rs;
            if ((lane & 1) == 0) scb[wrow + srow] = scale;
        }
        __syncwarp();

        // ---- rescale O, then O += P @ V (tf32, pure LDS + MMA) ----
        {
            float sc0 = scb[wrow + gid];
            float sc1 = scb[wrow + gid + 8];
#pragma unroll
            for (int ni = 0; ni < 8; ni++) {
                oacc[ni][0] *= sc0; oacc[ni][1] *= sc0;
                oacc[ni][2] *= sc1; oacc[ni][3] *= sc1;
            }
        }
#pragma unroll
        for (int ks = 0; ks < 8; ks++) {
            uint32_t pa[4];
            pa[0] = __float_as_uint(Ss[(wrow + gid) * ATS + ks * 8 + tig]);
            pa[1] = __float_as_uint(Ss[(wrow + gid + 8) * ATS + ks * 8 + tig]);
            pa[2] = __float_as_uint(Ss[(wrow + gid) * ATS + ks * 8 + tig + 4]);
            pa[3] = __float_as_uint(Ss[(wrow + gid + 8) * ATS + ks * 8 + tig + 4]);
#pragma unroll
            for (int ni = 0; ni < 8; ni++) {
                uint32_t vb[2];
                vb[0] = __float_as_uint(Vs[(ks * 8 + tig) * ATS + ni * 8 + gid]);
                vb[1] = __float_as_uint(Vs[(ks * 8 + tig + 4) * ATS + ni * 8 + gid]);
                mma_tf32(oacc[ni], pa, vb);
            }
        }
    }

    // ---- normalize and write out ----
    if ((lane & 1) == 0) lbuf[wrow + (lane >> 1)] = lsum;
    __syncwarp();
    float li0 = 1.f / lbuf[wrow + gid];
    float li1 = 1.f / lbuf[wrow + gid + 8];

#pragma unroll
    for (int ni = 0; ni < 8; ni++) {
        int col = h * HD + ni * 8 + 2 * tig;
        int row0 = b * SS + q0 + wrow + gid;
        *(float2*)(g_y + (size_t)row0 * DD + col) =
            make_float2(oacc[ni][0] * li0, oacc[ni][1] * li0);
        *(float2*)(g_y + (size_t)(row0 + 8) * DD + col) =
            make_float2(oacc[ni][2] * li1, oacc[ni][3] * li1);
    }
}

// ---------------------------------------------------------------------------
extern "C" void kernel_launch(void* const* d_in, const int* in_sizes, int n_in,
                              void* d_out, int out_size)
{
    const float* x    = (const float*)d_in[0];
    const float* ve   = (const float*)d_in[1];
    const float* cosp = (const float*)d_in[2];
    const float* sinp = (const float*)d_in[3];
    const float* Wq   = (const float*)d_in[4];
    const float* Wk   = (const float*)d_in[5];
    const float* Wv   = (const float*)d_in[6];
    const float* Wo   = (const float*)d_in[7];
    const float* Wg   = (const float*)d_in[8];
    const int*   win  = (const int*)d_in[9];
    float* out = (float*)d_out;

    float *pqkv, *py;
    cudaGetSymbolAddress((void**)&pqkv, g_qkv);
    cudaGetSymbolAddress((void**)&py, g_y);

    const int M = BB * SS;   // 4096

    // Fused QKV projection (tf32 tensor cores, pipelined)
    {
        dim3 g(QKVLD / 128, M / 128);
        gemm_tf32<1><<<g, 256>>>(x, Wq, Wk, Wv, pqkv, DD, QKVLD);
    }

    vgate_kernel<<<M, NKV * HD>>>(x, ve, Wg);
    rope_norm_kernel<<<M * (NH + NKV), HD>>>(cosp, sinp);

    // Tensor-core flash attention (bf16 hi/lo QK, tf32 PV)
    {
        int smem = (5 * TILEF + 128) * sizeof(float);   // 87552 B
        cudaFuncSetAttribute(attn_tc, cudaFuncAttributeMaxDynamicSharedMemorySize, smem);
        attn_tc<<<BB * NH * (SS / 64), 128, smem>>>(win);
    }

    // Output projection (tf32 tensor cores, pipelined)
    {
        dim3 g(DD / 128, M / 128);
        gemm_tf32<0><<<g, 256>>>(py, Wo, nullptr, nullptr, out, DD, DD);
    }
}